// round 10
// baseline (speedup 1.0000x reference)
#include <cuda_runtime.h>
#include <cuda_fp16.h>
#include <cstdint>

// ---------------------------------------------------------------------------
// FocDecoderRNN — fp16 tensor cores; GRU fused into the gi-GEMM epilogue via
// 64x192 gate-aligned tiles (all 3 gates of 64 columns per block, 48 acc regs,
// smem acc exchange). gi buffers eliminated entirely.
//   prep  : cvts + concat + compose_w2 + find_cells          (1 launch)
//   big2  : x1-splitK ∥ gh12                                 (1 launch)
//   reduce: x1 partials -> fp16 x1                           (1 launch)
//   fused : [layer1 + all cells] gi-GEMM + GRU -> h          (1 launch)
//   oGEMM : merged o1/o2                                     (1 launch)
//   assemble: y = bcast(o1) + scatter(o2)                    (1 launch)
// ---------------------------------------------------------------------------

#define BSZ  2048
#define MAXK 64

__device__ __half d_xh  [(size_t)BSZ * 4096];
__device__ __half d_hh  [BSZ * 256];
__device__ __half d_e1h [256 * 4096];
__device__ __half d_wi1h[768 * 256];
__device__ __half d_whhh[1536 * 256];
__device__ float  d_bhh [1536];
__device__ __half d_o1wh[64 * 256];
__device__ __half d_o2wh[64 * 256];
__device__ float  d_xp  [4 * BSZ * 256];
__device__ __half d_x1h [BSZ * 256];
__device__ float  d_gh12[(size_t)BSZ * 1536];
__device__ __half d_hh16[(size_t)(MAXK + 1) * BSZ * 256];
__device__ float  d_o   [(size_t)(MAXK + 1) * BSZ * 64];
__device__ __half d_w2ph[768 * 64];
__device__ float  d_b2p [768];
__device__ int    d_cx[MAXK], d_cy[MAXK], d_cmap[64];

// ---------------------------------------------------------------------------
__device__ __forceinline__ void mma_f16(float c[4], const uint32_t a[4], const uint32_t b[2])
{
    asm volatile(
        "mma.sync.aligned.m16n8k16.row.col.f32.f16.f16.f32 "
        "{%0,%1,%2,%3},{%4,%5,%6,%7},{%8,%9},{%0,%1,%2,%3};\n"
        : "+f"(c[0]), "+f"(c[1]), "+f"(c[2]), "+f"(c[3])
        : "r"(a[0]), "r"(a[1]), "r"(a[2]), "r"(a[3]), "r"(b[0]), "r"(b[1]));
}

__device__ __forceinline__ void cp16(uint32_t smem_addr, const void* gptr)
{
    asm volatile("cp.async.cg.shared.global [%0], [%1], 16;"
                 :: "r"(smem_addr), "l"(gptr));
}

__device__ __forceinline__ float sigf(float x) { return 1.f / (1.f + __expf(-x)); }

// ---------------------------------------------------------------------------
__device__ __forceinline__ void cvt_job(const float* __restrict__ s, __half* __restrict__ d,
                                        int grp)
{
    const float4 v = reinterpret_cast<const float4*>(s)[grp];
    reinterpret_cast<__half2*>(d)[grp * 2]     = __floats2half2_rn(v.x, v.y);
    reinterpret_cast<__half2*>(d)[grp * 2 + 1] = __floats2half2_rn(v.z, v.w);
}

__global__ void prep_kernel(const float* __restrict__ x,   const float* __restrict__ h,
                            const float* __restrict__ e1w, const float* __restrict__ wih1,
                            const float* __restrict__ o1w, const float* __restrict__ o2w,
                            const float* __restrict__ whh1, const float* __restrict__ whh2,
                            const float* __restrict__ bhh1, const float* __restrict__ bhh2,
                            const float* __restrict__ wih2, const float* __restrict__ e2w,
                            const float* __restrict__ e2b,  const float* __restrict__ bih2,
                            const float* __restrict__ fa,
                            __half* __restrict__ xh,  __half* __restrict__ hh,
                            __half* __restrict__ e1h, __half* __restrict__ wi1h,
                            __half* __restrict__ o1wh, __half* __restrict__ o2wh,
                            __half* __restrict__ whhh, float* __restrict__ bhh,
                            __half* __restrict__ w2ph, float* __restrict__ b2p,
                            int* __restrict__ cx, int* __restrict__ cy, int* __restrict__ cmap,
                            int B)
{
    const int bid = blockIdx.x;
    const int tid = threadIdx.x;
    const int b0 = B * 4;
    const int b1 = b0 + B / 4;
    const int b2 = b1 + 1024;
    const int b3 = b2 + 192;
    const int b4 = b3 + 16;
    const int b5 = b4 + 16;
    const int b6 = b5 + 384;
    const int b7 = b6 + 192;
    if (bid < b0)      { cvt_job(x,    xh,   bid * 256 + tid); }
    else if (bid < b1) { cvt_job(h,    hh,   (bid - b0) * 256 + tid); }
    else if (bid < b2) { cvt_job(e1w,  e1h,  (bid - b1) * 256 + tid); }
    else if (bid < b3) { cvt_job(wih1, wi1h, (bid - b2) * 256 + tid); }
    else if (bid < b4) { cvt_job(o1w,  o1wh, (bid - b3) * 256 + tid); }
    else if (bid < b5) { cvt_job(o2w,  o2wh, (bid - b4) * 256 + tid); }
    else if (bid < b6) {
        const int i = (bid - b5) * 256 + tid;
        const int e = i * 4, row = e >> 8, col = e & 255;
        const float* src = (row < 768) ? (whh1 + row * 256 + col)
                                       : (whh2 + (row - 768) * 256 + col);
        const float4 v = *reinterpret_cast<const float4*>(src);
        reinterpret_cast<__half2*>(whhh)[i * 2]     = __floats2half2_rn(v.x, v.y);
        reinterpret_cast<__half2*>(whhh)[i * 2 + 1] = __floats2half2_rn(v.z, v.w);
        if (i < 1536) bhh[i] = (i < 768) ? bhh1[i] : bhh2[i - 768];
    } else if (bid < b7) {
        const int n = (bid - b6) * 4 + (tid >> 6);
        const int t = tid & 63;
        float s = 0.f;
        for (int c = 0; c < 256; c++)
            s += wih2[n * 256 + c] * e2w[c * 64 + t];
        w2ph[n * 64 + t] = __float2half_rn(s);
        if (t == 0) {
            float sb = 0.f;
            for (int c = 0; c < 256; c++) sb += wih2[n * 256 + c] * e2b[c];
            b2p[n] = bih2[n] + sb;
        }
    } else {
        if (tid == 0) {
            for (int i = 0; i < 64; i++) cmap[i] = -1;
            int k = 0;
            for (int i = 0; i < 8; i++)
                for (int j = 0; j < 8; j++)
                    if (fa[i * 8 + j] > 0.5f) { cx[k] = i; cy[k] = j; cmap[i * 8 + j] = k; k++; }
        }
    }
}

// ---------------------------------------------------------------------------
// Generic 128xNT fp16 GEMM core (cp.async 3-stage, K-slab 32) — used by big2
// (x1 splitK, gh12) and the merged o-GEMM.
#define CAS  3
#define ROWH 40

template<int NT, int HOUT>
__device__ __forceinline__
void gemm_dev(const __half* __restrict__ A, const __half* __restrict__ Bw,
              const float* __restrict__ bias, void* __restrict__ Cv,
              int N, int K, int lda, int ldb,
              long long sAz, long long sBz, long long sCz,
              int bx, int by, int bz)
{
    constexpr int STG_A = 128 * ROWH;
    constexpr int STG_B = NT * ROWH;
    constexpr int WNW   = (NT == 128) ? 4 : 2;
    constexpr int MF    = (NT == 128) ? 4 : 2;

    extern __shared__ __half smh[];
    const uint32_t smBase = (uint32_t)__cvta_generic_to_shared(smh);

    const int bm = by * 128;
    const int bn = bx * NT;
    A += (long long)bz * sAz;
    Bw += (long long)bz * sBz;

    const int tid  = threadIdx.x;
    const int lane = tid & 31;
    const int wid  = tid >> 5;
    const int wm   = wid / WNW;
    const int wn   = wid % WNW;
    const int g    = lane >> 2;
    const int t2   = (lane & 3) * 2;
    const int lr   = tid >> 1;
    const int lk   = (tid & 1) * 16;
    const int br   = (NT == 128) ? (tid >> 1) : (tid >> 2);
    const int bc   = (NT == 128) ? (tid & 1) * 16 : (tid & 3) * 8;

    float acc[MF][4][4];
#pragma unroll
    for (int i = 0; i < MF; i++)
#pragma unroll
        for (int j = 0; j < 4; j++)
#pragma unroll
            for (int q = 0; q < 4; q++) acc[i][j][q] = 0.f;

    auto issue = [&](int stg, int k0) {
        const __half* ap = A + (long long)(bm + lr) * lda + k0 + lk;
        const uint32_t da = smBase + 2u * (stg * STG_A + lr * ROWH + lk);
        cp16(da,      ap);
        cp16(da + 16, ap + 8);
        const __half* bp = Bw + (long long)(bn + br) * ldb + k0 + bc;
        const uint32_t db = smBase + 2u * (CAS * STG_A + stg * STG_B + br * ROWH + bc);
        cp16(db, bp);
        if (NT == 128) cp16(db + 16, bp + 8);
    };

    const int nIter = K >> 5;
#pragma unroll
    for (int s = 0; s < CAS - 1; s++) {
        if (s < nIter) issue(s, s * 32);
        asm volatile("cp.async.commit_group;");
    }

    for (int it = 0; it < nIter; it++) {
        const int cur = it % CAS;
        asm volatile("cp.async.wait_group %0;" :: "n"(CAS - 2));
        __syncthreads();

        const __half* Ab = smh + cur * STG_A;
        const __half* Bb = smh + CAS * STG_A + cur * STG_B;
#pragma unroll
        for (int kk = 0; kk < 32; kk += 16) {
            uint32_t af[MF][4], bf[4][2];
#pragma unroll
            for (int i = 0; i < MF; i++) {
                const int m = wm * (MF * 16) + i * 16;
                af[i][0] = *reinterpret_cast<const uint32_t*>(Ab + (m + g) * ROWH + kk + t2);
                af[i][1] = *reinterpret_cast<const uint32_t*>(Ab + (m + 8 + g) * ROWH + kk + t2);
                af[i][2] = *reinterpret_cast<const uint32_t*>(Ab + (m + g) * ROWH + kk + t2 + 8);
                af[i][3] = *reinterpret_cast<const uint32_t*>(Ab + (m + 8 + g) * ROWH + kk + t2 + 8);
            }
#pragma unroll
            for (int j = 0; j < 4; j++) {
                const int n = wn * 32 + j * 8;
                bf[j][0] = *reinterpret_cast<const uint32_t*>(Bb + (n + g) * ROWH + kk + t2);
                bf[j][1] = *reinterpret_cast<const uint32_t*>(Bb + (n + g) * ROWH + kk + t2 + 8);
            }
#pragma unroll
            for (int i = 0; i < MF; i++)
#pragma unroll
                for (int j = 0; j < 4; j++) mma_f16(acc[i][j], af[i], bf[j]);
        }
        const int nk = it + CAS - 1;
        if (nk < nIter) issue(nk % CAS, nk * 32);
        asm volatile("cp.async.commit_group;");
    }

    float* Cf = (float*)Cv;
    __half* Ch = (__half*)Cv;
#pragma unroll
    for (int i = 0; i < MF; i++) {
        const int row0 = bm + wm * (MF * 16) + i * 16 + g;
#pragma unroll
        for (int j = 0; j < 4; j++) {
            const int col = bn + wn * 32 + j * 8 + t2;
            float bz0 = 0.f, bz1 = 0.f;
            if (bias) { bz0 = __ldg(&bias[col]); bz1 = __ldg(&bias[col + 1]); }
            const float v0 = acc[i][j][0] + bz0, v1 = acc[i][j][1] + bz1;
            const float v2 = acc[i][j][2] + bz0, v3 = acc[i][j][3] + bz1;
            if (HOUT == 0) {
                float* C = Cf + (long long)bz * sCz;
                *reinterpret_cast<float2*>(&C[(long long)row0 * N + col]) = make_float2(v0, v1);
                *reinterpret_cast<float2*>(&C[(long long)(row0 + 8) * N + col]) = make_float2(v2, v3);
            } else {
                __half* C = Ch + (long long)bz * sCz;
                *reinterpret_cast<__half2*>(&C[(long long)row0 * N + col]) =
                    __floats2half2_rn(v0, v1);
                *reinterpret_cast<__half2*>(&C[(long long)(row0 + 8) * N + col]) =
                    __floats2half2_rn(v2, v3);
            }
        }
    }
}

// big2: x1-splitK (128 blocks) ∥ gh12 (192 blocks)
__global__ __launch_bounds__(256)
void big2(const __half* __restrict__ xh, const __half* __restrict__ e1h,
          const __half* __restrict__ hh, const __half* __restrict__ whhh,
          const float* __restrict__ bhh,
          float* __restrict__ xp, float* __restrict__ gh12,
          int MB, int nX1, int B)
{
    const int i = blockIdx.x;
    if (i < nX1) {
        const int bx = i & 1, r = i >> 1;
        gemm_dev<128, 0>(xh, e1h, nullptr, xp, 256, 1024, 4096, 4096,
                         1024, 1024, (long long)B * 256, bx, r % MB, r / MB);
    } else {
        const int j = i - nX1;
        gemm_dev<128, 0>(hh, whhh, bhh, gh12, 1536, 256, 256, 256,
                         0, 0, 0, j % 12, j / 12, 0);
    }
}

// merged o GEMM: z=0 -> o1w/bias1; z>0 -> o2w/bias2
__global__ __launch_bounds__(256)
void o_gemm(const __half* __restrict__ A,
            const __half* __restrict__ Bw, const __half* __restrict__ Bw2,
            const float* __restrict__ bias, const float* __restrict__ bias2,
            float* __restrict__ C, int B)
{
    const __half* B_ = (blockIdx.z > 0) ? Bw2 : Bw;
    const float* bi  = (blockIdx.z > 0) ? bias2 : bias;
    gemm_dev<64, 0>(A, B_, bi, C, 64, 256, 256, 256,
                    (long long)B * 256, 0, (long long)B * 64,
                    blockIdx.x, blockIdx.y, blockIdx.z);
}

// ---------------------------------------------------------------------------
// Fused gi-GEMM + GRU. Tile 64(M) x 192(N = 3 gates x 64 cols). 8 warps as
// 2m x 4n (warp 32x48, NF=6, 48 acc regs). After mainloop, acc staged via
// smem (stride 196 = bank-rotating) so threads read (r,z,n) triples; GRU
// applied with gh12/h0; h written to out (fp32) + hh16 (fp16).
//   z=0: layer1 (A=x1h, K=256, B=wi1h, bias=bih1, gh cols 0..767, slot 0)
//   z>0: cell z-1 (A=patch gather from xh, K=64, B=w2ph, bias=b2p, gh 768+)
#define FSTG ((64 + 192) * ROWH)     // halves per stage

__global__ __launch_bounds__(256)
void gru_gemm_fused(const __half* __restrict__ x1h, const __half* __restrict__ wi1h,
                    const float* __restrict__ bih1,
                    const __half* __restrict__ xh, const __half* __restrict__ w2ph,
                    const float* __restrict__ b2p,
                    const float* __restrict__ gh12, const float* __restrict__ h0,
                    float* __restrict__ hout, __half* __restrict__ h16,
                    const int* __restrict__ cxs, const int* __restrict__ cys, int B)
{
    extern __shared__ __half smh[];
    const uint32_t smBase = (uint32_t)__cvta_generic_to_shared(smh);

    const int z  = blockIdx.z;
    const bool isL1 = (z == 0);
    const int bm = blockIdx.y * 64;
    const int bn = blockIdx.x * 64;          // gate-column slice
    const int K    = isL1 ? 256 : 64;
    const int ldb  = K;
    const __half* A  = isL1 ? x1h : xh;
    const __half* Bw = isL1 ? wi1h : w2ph;
    const float* bias = isL1 ? bih1 : b2p;
    const int ghOff = isL1 ? 0 : 768;
    int cellBase = 0;
    if (!isL1) cellBase = cxs[z - 1] * 512 + cys[z - 1] * 8;

    const int tid  = threadIdx.x;
    const int lane = tid & 31;
    const int wid  = tid >> 5;
    const int wm   = wid >> 2;               // 0..1
    const int wn   = wid & 3;                // 0..3
    const int g    = lane >> 2;
    const int t2   = (lane & 3) * 2;
    const int lr   = tid >> 2;               // 0..63 loader row
    const int lc   = (tid & 3) * 8;          // 0..24 loader col (halves)

    float acc[2][6][4];
#pragma unroll
    for (int i = 0; i < 2; i++)
#pragma unroll
        for (int j = 0; j < 6; j++)
#pragma unroll
            for (int q = 0; q < 4; q++) acc[i][j][q] = 0.f;

    auto issue = [&](int stg, int k0) {
        // A: 64 x 32 halves, 1 cp16/thread
        const __half* ap;
        if (isL1) ap = A + (long long)(bm + lr) * 256 + k0 + lc;
        else      ap = A + (long long)(bm + lr) * 4096 + cellBase + (((k0 + lc) >> 3) << 6);
        cp16(smBase + 2u * (stg * FSTG + lr * ROWH + lc), ap);
        // B: 3 gates x 64 rows x 32 halves, 3 cp16/thread
#pragma unroll
        for (int s = 0; s < 3; s++) {
            const __half* bp = Bw + (long long)(s * 256 + bn + lr) * ldb + k0 + lc;
            cp16(smBase + 2u * (stg * FSTG + 64 * ROWH + (s * 64 + lr) * ROWH + lc), bp);
        }
    };

    const int nIter = K >> 5;
#pragma unroll
    for (int s = 0; s < CAS - 1; s++) {
        if (s < nIter) issue(s, s * 32);
        asm volatile("cp.async.commit_group;");
    }

    for (int it = 0; it < nIter; it++) {
        const int cur = it % CAS;
        asm volatile("cp.async.wait_group %0;" :: "n"(CAS - 2));
        __syncthreads();

        const __half* Ab = smh + cur * FSTG;
        const __half* Bb = smh + cur * FSTG + 64 * ROWH;
#pragma unroll
        for (int kk = 0; kk < 32; kk += 16) {
            uint32_t af[2][4], bf[6][2];
#pragma unroll
            for (int i = 0; i < 2; i++) {
                const int m = wm * 32 + i * 16;
                af[i][0] = *reinterpret_cast<const uint32_t*>(Ab + (m + g) * ROWH + kk + t2);
                af[i][1] = *reinterpret_cast<const uint32_t*>(Ab + (m + 8 + g) * ROWH + kk + t2);
                af[i][2] = *reinterpret_cast<const uint32_t*>(Ab + (m + g) * ROWH + kk + t2 + 8);
                af[i][3] = *reinterpret_cast<const uint32_t*>(Ab + (m + 8 + g) * ROWH + kk + t2 + 8);
            }
#pragma unroll
            for (int j = 0; j < 6; j++) {
                const int n = wn * 48 + j * 8;
                bf[j][0] = *reinterpret_cast<const uint32_t*>(Bb + (n + g) * ROWH + kk + t2);
                bf[j][1] = *reinterpret_cast<const uint32_t*>(Bb + (n + g) * ROWH + kk + t2 + 8);
            }
#pragma unroll
            for (int i = 0; i < 2; i++)
#pragma unroll
                for (int j = 0; j < 6; j++) mma_f16(acc[i][j], af[i], bf[j]);
        }
        const int nk = it + CAS - 1;
        if (nk < nIter) issue(nk % CAS, nk * 32);
        asm volatile("cp.async.commit_group;");
    }

    // ---- stage acc through smem so threads can read gate triples ----
    __syncthreads();
    float* smacc = reinterpret_cast<float*>(smh);      // [64][196]
#pragma unroll
    for (int i = 0; i < 2; i++)
#pragma unroll
        for (int j = 0; j < 6; j++)
#pragma unroll
            for (int q = 0; q < 4; q++) {
                const int row = wm * 32 + i * 16 + g + ((q >> 1) << 3);
                const int col = wn * 48 + j * 8 + t2 + (q & 1);
                smacc[row * 196 + col] = acc[i][j][q];
            }
    __syncthreads();

    // ---- GRU epilogue: thread -> (row, 16 cols) ----
    const int row = tid >> 2;
    const int c0  = (tid & 3) * 16;
    const long long b = bm + row;
    const float* ghp = gh12 + b * 1536 + ghOff;
    const long long obase = (long long)z * B * 256 + b * 256 + bn;

#pragma unroll
    for (int cc = 0; cc < 16; cc += 4) {
        float4 hv = *reinterpret_cast<const float4*>(h0 + b * 256 + bn + c0 + cc);
        float o[4];
#pragma unroll
        for (int u = 0; u < 4; u++) {
            const int c = c0 + cc + u;
            const int gc = bn + c;
            const float gir = smacc[row * 196 + c]       + __ldg(&bias[gc]);
            const float giz = smacc[row * 196 + 64 + c]  + __ldg(&bias[256 + gc]);
            const float gin = smacc[row * 196 + 128 + c] + __ldg(&bias[512 + gc]);
            const float hr = ghp[gc], hz = ghp[256 + gc], hn = ghp[512 + gc];
            const float rr = sigf(gir + hr);
            const float zz = sigf(giz + hz);
            const float nn = tanhf(gin + rr * hn);
            const float hu = (u == 0) ? hv.x : (u == 1) ? hv.y : (u == 2) ? hv.z : hv.w;
            o[u] = (1.f - zz) * nn + zz * hu;
        }
        *reinterpret_cast<float4*>(hout + obase + c0 + cc) =
            make_float4(o[0], o[1], o[2], o[3]);
        reinterpret_cast<__half2*>(h16 + obase + c0 + cc)[0] = __floats2half2_rn(o[0], o[1]);
        reinterpret_cast<__half2*>(h16 + obase + c0 + cc)[1] = __floats2half2_rn(o[2], o[3]);
    }
}

// ---------------------------------------------------------------------------
__global__ void reduce_x1_kernel(const float* __restrict__ P, const float* __restrict__ bias,
                                 __half* __restrict__ x1, int n4)
{
    const int idx = blockIdx.x * blockDim.x + threadIdx.x;
    if (idx >= n4) return;
    const float4 p0 = *reinterpret_cast<const float4*>(P + (size_t)0 * BSZ * 256 + idx * 4);
    const float4 p1 = *reinterpret_cast<const float4*>(P + (size_t)1 * BSZ * 256 + idx * 4);
    const float4 p2 = *reinterpret_cast<const float4*>(P + (size_t)2 * BSZ * 256 + idx * 4);
    const float4 p3 = *reinterpret_cast<const float4*>(P + (size_t)3 * BSZ * 256 + idx * 4);
    const int j0 = (idx * 4) & 255;
    const float4 b = *reinterpret_cast<const float4*>(bias + j0);
    reinterpret_cast<__half2*>(x1)[idx * 2] =
        __floats2half2_rn(p0.x + p1.x + p2.x + p3.x + b.x,
                          p0.y + p1.y + p2.y + p3.y + b.y);
    reinterpret_cast<__half2*>(x1)[idx * 2 + 1] =
        __floats2half2_rn(p0.z + p1.z + p2.z + p3.z + b.z,
                          p0.w + p1.w + p2.w + p3.w + b.w);
}

// ---------------------------------------------------------------------------
__global__ void assemble_y_kernel(const float* __restrict__ o1, const float* __restrict__ o2,
                                  const int* __restrict__ cmap, float* __restrict__ y, int n4)
{
    const int idx = blockIdx.x * blockDim.x + threadIdx.x;
    if (idx >= n4) return;
    const int b   = idx >> 10;
    const int rem = idx & 1023;
    const int i   = rem >> 4;
    const int j0  = (rem & 15) * 4;
    const float v = __ldg(&o1[b * 64 + i]);
    float4 r = make_float4(v, v, v, v);
    const int k = cmap[(i >> 3) * 8 + (j0 >> 3)];
    if (k >= 0) {
        const int t = (i & 7) * 8 + (j0 & 7);
        const float4 a = *reinterpret_cast<const float4*>(o2 + ((long long)k * BSZ + b) * 64 + t);
        r.x += a.x; r.y += a.y; r.z += a.z; r.w += a.w;
    }
    *reinterpret_cast<float4*>(y + (long long)idx * 4) = r;
}

// ---------------------------------------------------------------------------
extern "C" void kernel_launch(void* const* d_in, const int* in_sizes, int n_in,
                              void* d_out, int out_size)
{
    const float* x    = (const float*)d_in[0];
    const float* h    = (const float*)d_in[1];
    const float* fa   = (const float*)d_in[2];
    const float* e1w  = (const float*)d_in[3];
    const float* e1b  = (const float*)d_in[4];
    const float* wih1 = (const float*)d_in[5];
    const float* whh1 = (const float*)d_in[6];
    const float* bih1 = (const float*)d_in[7];
    const float* bhh1 = (const float*)d_in[8];
    const float* o1w  = (const float*)d_in[9];
    const float* o1b  = (const float*)d_in[10];
    const float* e2w  = (const float*)d_in[11];
    const float* e2b  = (const float*)d_in[12];
    const float* wih2 = (const float*)d_in[13];
    const float* whh2 = (const float*)d_in[14];
    const float* bih2 = (const float*)d_in[15];
    const float* bhh2 = (const float*)d_in[16];
    const float* o2w  = (const float*)d_in[17];
    const float* o2b  = (const float*)d_in[18];
    float* out = (float*)d_out;

    const int B = in_sizes[0] / 4096;                  // 2048
    const long long YOFF = (long long)B * 4096;
    int Kc = (int)(((long long)out_size - YOFF) / ((long long)B * 256)) - 1;
    if (Kc < 0) Kc = 0;
    if (Kc > MAXK) Kc = MAXK;

    __half *p_xh, *p_hh, *p_e1h, *p_wi1h, *p_whhh, *p_o1wh, *p_o2wh,
           *p_x1h, *p_hh16, *p_w2ph;
    float *p_bhh, *p_xp, *p_gh12, *p_o, *p_b2p;
    int *p_cx, *p_cy, *p_cmap;
    cudaGetSymbolAddress((void**)&p_xh,   d_xh);
    cudaGetSymbolAddress((void**)&p_hh,   d_hh);
    cudaGetSymbolAddress((void**)&p_e1h,  d_e1h);
    cudaGetSymbolAddress((void**)&p_wi1h, d_wi1h);
    cudaGetSymbolAddress((void**)&p_whhh, d_whhh);
    cudaGetSymbolAddress((void**)&p_bhh,  d_bhh);
    cudaGetSymbolAddress((void**)&p_o1wh, d_o1wh);
    cudaGetSymbolAddress((void**)&p_o2wh, d_o2wh);
    cudaGetSymbolAddress((void**)&p_xp,   d_xp);
    cudaGetSymbolAddress((void**)&p_x1h,  d_x1h);
    cudaGetSymbolAddress((void**)&p_gh12, d_gh12);
    cudaGetSymbolAddress((void**)&p_hh16, d_hh16);
    cudaGetSymbolAddress((void**)&p_o,    d_o);
    cudaGetSymbolAddress((void**)&p_w2ph, d_w2ph);
    cudaGetSymbolAddress((void**)&p_b2p,  d_b2p);
    cudaGetSymbolAddress((void**)&p_cx,   d_cx);
    cudaGetSymbolAddress((void**)&p_cy,   d_cy);
    cudaGetSymbolAddress((void**)&p_cmap, d_cmap);

    const int SMB128 = 2 * CAS * (128 * ROWH + 128 * ROWH);  // 61440
    const int SMB64  = 2 * CAS * (128 * ROWH + 64 * ROWH);   // 46080
    const int SMBF   = 2 * CAS * FSTG;                       // 61440
    cudaFuncSetAttribute((const void*)big2,           cudaFuncAttributeMaxDynamicSharedMemorySize, SMB128);
    cudaFuncSetAttribute((const void*)o_gemm,         cudaFuncAttributeMaxDynamicSharedMemorySize, SMB64);
    cudaFuncSetAttribute((const void*)gru_gemm_fused, cudaFuncAttributeMaxDynamicSharedMemorySize, SMBF);

    float* yh0 = out + YOFF;
    const int MB = B / 128;                       // 16
    const int nPrep = B * 4 + B / 4 + 1024 + 192 + 16 + 16 + 384 + 192 + 1;

    // 1) prep
    prep_kernel<<<nPrep, 256>>>(x, h, e1w, wih1, o1w, o2w, whh1, whh2, bhh1, bhh2,
                                wih2, e2w, e2b, bih2, fa,
                                p_xh, p_hh, p_e1h, p_wi1h, p_o1wh, p_o2wh,
                                p_whhh, p_bhh, p_w2ph, p_b2p,
                                p_cx, p_cy, p_cmap, B);

    // 2) x1-splitK ∥ gh12
    const int nX1 = 2 * MB * 4;
    big2<<<nX1 + 12 * MB, 256, SMB128>>>(p_xh, p_e1h, p_hh, p_whhh, p_bhh,
                                         p_xp, p_gh12, MB, nX1, B);

    // 3) reduce -> fp16 x1
    reduce_x1_kernel<<<(B * 64 + 255) / 256, 256>>>(p_xp, e1b, p_x1h, B * 64);

    // 4) fused gi-GEMM + GRU for layer1 (z=0) and all cells (z=1..Kc)
    gru_gemm_fused<<<dim3(4, B / 64, Kc + 1), 256, SMBF>>>(
        p_x1h, p_wi1h, bih1, p_xh, p_w2ph, p_b2p,
        p_gh12, h, yh0, p_hh16, p_cx, p_cy, B);

    // 5) merged o GEMM
    o_gemm<<<dim3(1, MB, Kc + 1), 256, SMB64>>>(p_hh16, p_o1wh, p_o2wh, o1b, o2b, p_o, B);

    // 6) y = bcast(o1) + scatter(o2)
    assemble_y_kernel<<<(B * 1024 + 255) / 256, 256>>>(p_o, p_o + (long long)B * 64,
                                                       p_cmap, out, B * 1024);
}

// round 11
// speedup vs baseline: 1.4340x; 1.4340x over previous
#include <cuda_runtime.h>
#include <cuda_fp16.h>
#include <cstdint>

// ---------------------------------------------------------------------------
// FocDecoderRNN — R9 structure (fp16 m16n8k16 engine, horizontal fusion).
// R11 delta: gi1 (64-row tiles) runs CONCURRENTLY with gru-cells in one wide
// launch; gru layer-1 follows. Fused-GRU-in-GEMM abandoned (R4/R7/R10).
// ---------------------------------------------------------------------------

#define BSZ  2048
#define MAXK 64

__device__ __half d_xh  [(size_t)BSZ * 4096];
__device__ __half d_hh  [BSZ * 256];
__device__ __half d_e1h [256 * 4096];
__device__ __half d_wi1h[768 * 256];
__device__ __half d_whhh[1536 * 256];
__device__ float  d_bhh [1536];
__device__ __half d_o1wh[64 * 256];
__device__ __half d_o2wh[64 * 256];
__device__ float  d_xp  [4 * BSZ * 256];
__device__ __half d_x1h [BSZ * 256];
__device__ float  d_gh12[(size_t)BSZ * 1536];
__device__ __half d_gi1h[BSZ * 768];
__device__ __half d_gi2h[(size_t)MAXK * BSZ * 768];
__device__ __half d_hh16[(size_t)(MAXK + 1) * BSZ * 256];
__device__ float  d_o   [(size_t)(MAXK + 1) * BSZ * 64];
__device__ __half d_w2ph[768 * 64];
__device__ float  d_b2p [768];
__device__ int    d_cx[MAXK], d_cy[MAXK], d_cmap[64];

// ---------------------------------------------------------------------------
__device__ __forceinline__ void mma_f16(float c[4], const uint32_t a[4], const uint32_t b[2])
{
    asm volatile(
        "mma.sync.aligned.m16n8k16.row.col.f32.f16.f16.f32 "
        "{%0,%1,%2,%3},{%4,%5,%6,%7},{%8,%9},{%0,%1,%2,%3};\n"
        : "+f"(c[0]), "+f"(c[1]), "+f"(c[2]), "+f"(c[3])
        : "r"(a[0]), "r"(a[1]), "r"(a[2]), "r"(a[3]), "r"(b[0]), "r"(b[1]));
}

__device__ __forceinline__ void cp16(uint32_t smem_addr, const void* gptr)
{
    asm volatile("cp.async.cg.shared.global [%0], [%1], 16;"
                 :: "r"(smem_addr), "l"(gptr));
}

__device__ __forceinline__ float sigf(float x) { return 1.f / (1.f + __expf(-x)); }

// ---------------------------------------------------------------------------
__device__ __forceinline__ void cvt_job(const float* __restrict__ s, __half* __restrict__ d,
                                        int grp)
{
    const float4 v = reinterpret_cast<const float4*>(s)[grp];
    reinterpret_cast<__half2*>(d)[grp * 2]     = __floats2half2_rn(v.x, v.y);
    reinterpret_cast<__half2*>(d)[grp * 2 + 1] = __floats2half2_rn(v.z, v.w);
}

__global__ void prep_kernel(const float* __restrict__ x,   const float* __restrict__ h,
                            const float* __restrict__ e1w, const float* __restrict__ wih1,
                            const float* __restrict__ o1w, const float* __restrict__ o2w,
                            const float* __restrict__ whh1, const float* __restrict__ whh2,
                            const float* __restrict__ bhh1, const float* __restrict__ bhh2,
                            const float* __restrict__ wih2, const float* __restrict__ e2w,
                            const float* __restrict__ e2b,  const float* __restrict__ bih2,
                            const float* __restrict__ fa,
                            __half* __restrict__ xh,  __half* __restrict__ hh,
                            __half* __restrict__ e1h, __half* __restrict__ wi1h,
                            __half* __restrict__ o1wh, __half* __restrict__ o2wh,
                            __half* __restrict__ whhh, float* __restrict__ bhh,
                            __half* __restrict__ w2ph, float* __restrict__ b2p,
                            int* __restrict__ cx, int* __restrict__ cy, int* __restrict__ cmap,
                            int B)
{
    const int bid = blockIdx.x;
    const int tid = threadIdx.x;
    const int b0 = B * 4;
    const int b1 = b0 + B / 4;
    const int b2 = b1 + 1024;
    const int b3 = b2 + 192;
    const int b4 = b3 + 16;
    const int b5 = b4 + 16;
    const int b6 = b5 + 384;
    const int b7 = b6 + 192;
    if (bid < b0)      { cvt_job(x,    xh,   bid * 256 + tid); }
    else if (bid < b1) { cvt_job(h,    hh,   (bid - b0) * 256 + tid); }
    else if (bid < b2) { cvt_job(e1w,  e1h,  (bid - b1) * 256 + tid); }
    else if (bid < b3) { cvt_job(wih1, wi1h, (bid - b2) * 256 + tid); }
    else if (bid < b4) { cvt_job(o1w,  o1wh, (bid - b3) * 256 + tid); }
    else if (bid < b5) { cvt_job(o2w,  o2wh, (bid - b4) * 256 + tid); }
    else if (bid < b6) {
        const int i = (bid - b5) * 256 + tid;
        const int e = i * 4, row = e >> 8, col = e & 255;
        const float* src = (row < 768) ? (whh1 + row * 256 + col)
                                       : (whh2 + (row - 768) * 256 + col);
        const float4 v = *reinterpret_cast<const float4*>(src);
        reinterpret_cast<__half2*>(whhh)[i * 2]     = __floats2half2_rn(v.x, v.y);
        reinterpret_cast<__half2*>(whhh)[i * 2 + 1] = __floats2half2_rn(v.z, v.w);
        if (i < 1536) bhh[i] = (i < 768) ? bhh1[i] : bhh2[i - 768];
    } else if (bid < b7) {
        const int n = (bid - b6) * 4 + (tid >> 6);
        const int t = tid & 63;
        float s = 0.f;
        for (int c = 0; c < 256; c++)
            s += wih2[n * 256 + c] * e2w[c * 64 + t];
        w2ph[n * 64 + t] = __float2half_rn(s);
        if (t == 0) {
            float sb = 0.f;
            for (int c = 0; c < 256; c++) sb += wih2[n * 256 + c] * e2b[c];
            b2p[n] = bih2[n] + sb;
        }
    } else {
        if (tid == 0) {
            for (int i = 0; i < 64; i++) cmap[i] = -1;
            int k = 0;
            for (int i = 0; i < 8; i++)
                for (int j = 0; j < 8; j++)
                    if (fa[i * 8 + j] > 0.5f) { cx[k] = i; cy[k] = j; cmap[i * 8 + j] = k; k++; }
        }
    }
}

// ---------------------------------------------------------------------------
// FP16 GEMM-NT device core (cp.async 3-stage, K-slab 32, m16n8k16).
//   MT: M tile (128 or 64).  NT: N tile (128 or 64).
//   AMODE 1: A = patch gather from x (K=64 path).
#define CAS  3
#define ROWH 40

template<int AMODE, int NT, int HOUT, int MT>
__device__ __forceinline__
void gemm_dev(const __half* __restrict__ A, const __half* __restrict__ Bw,
              const float* __restrict__ bias, void* __restrict__ Cv,
              int N, int K, int lda, int ldb,
              long long sAz, long long sBz, long long sCz,
              const int* __restrict__ cxs, const int* __restrict__ cys,
              int bx, int by, int bz)
{
    constexpr int STG_A = MT * ROWH;
    constexpr int STG_B = NT * ROWH;
    constexpr int WNW   = (NT == 128) ? 4 : 2;
    constexpr int MF    = MT * WNW / 128;     // 128/128->4, 64/128->2, 128/64->2

    extern __shared__ __half smh[];
    const uint32_t smBase = (uint32_t)__cvta_generic_to_shared(smh);

    const int bm = by * MT;
    const int bn = bx * NT;
    int cellBase = 0;
    if (AMODE == 1) cellBase = cxs[bz] * 512 + cys[bz] * 8;
    if (AMODE == 0) A += (long long)bz * sAz;
    Bw += (long long)bz * sBz;

    const int tid  = threadIdx.x;
    const int lane = tid & 31;
    const int wid  = tid >> 5;
    const int wm   = wid / WNW;
    const int wn   = wid % WNW;
    const int g    = lane >> 2;
    const int t2   = (lane & 3) * 2;
    const int alr  = (MT == 128) ? (tid >> 1) : (tid >> 2);
    const int alk  = (MT == 128) ? (tid & 1) * 16 : (tid & 3) * 8;
    const int br   = (NT == 128) ? (tid >> 1) : (tid >> 2);
    const int bc   = (NT == 128) ? (tid & 1) * 16 : (tid & 3) * 8;

    float acc[MF][4][4];
#pragma unroll
    for (int i = 0; i < MF; i++)
#pragma unroll
        for (int j = 0; j < 4; j++)
#pragma unroll
            for (int q = 0; q < 4; q++) acc[i][j][q] = 0.f;

    auto issue = [&](int stg, int k0) {
        const __half *ap0, *ap1;
        if (AMODE == 0) {
            ap0 = A + (long long)(bm + alr) * lda + k0 + alk;
            ap1 = ap0 + 8;
        } else {
            const int tt = k0 + alk;
            const __half* base = A + (long long)(bm + alr) * 4096 + cellBase;
            ap0 = base + ((tt >> 3) << 6);
            ap1 = base + (((tt + 8) >> 3) << 6);
        }
        const uint32_t da = smBase + 2u * (stg * STG_A + alr * ROWH + alk);
        cp16(da, ap0);
        if (MT == 128) cp16(da + 16, ap1);
        const __half* bp = Bw + (long long)(bn + br) * ldb + k0 + bc;
        const uint32_t db = smBase + 2u * (CAS * STG_A + stg * STG_B + br * ROWH + bc);
        cp16(db, bp);
        if (NT == 128) cp16(db + 16, bp + 8);
    };

    const int nIter = K >> 5;
#pragma unroll
    for (int s = 0; s < CAS - 1; s++) {
        if (s < nIter) issue(s, s * 32);
        asm volatile("cp.async.commit_group;");
    }

    for (int it = 0; it < nIter; it++) {
        const int cur = it % CAS;
        asm volatile("cp.async.wait_group %0;" :: "n"(CAS - 2));
        __syncthreads();

        const __half* Ab = smh + cur * STG_A;
        const __half* Bb = smh + CAS * STG_A + cur * STG_B;
#pragma unroll
        for (int kk = 0; kk < 32; kk += 16) {
            uint32_t af[MF][4], bf[4][2];
#pragma unroll
            for (int i = 0; i < MF; i++) {
                const int m = wm * (MF * 16) + i * 16;
                af[i][0] = *reinterpret_cast<const uint32_t*>(Ab + (m + g) * ROWH + kk + t2);
                af[i][1] = *reinterpret_cast<const uint32_t*>(Ab + (m + 8 + g) * ROWH + kk + t2);
                af[i][2] = *reinterpret_cast<const uint32_t*>(Ab + (m + g) * ROWH + kk + t2 + 8);
                af[i][3] = *reinterpret_cast<const uint32_t*>(Ab + (m + 8 + g) * ROWH + kk + t2 + 8);
            }
#pragma unroll
            for (int j = 0; j < 4; j++) {
                const int n = wn * 32 + j * 8;
                bf[j][0] = *reinterpret_cast<const uint32_t*>(Bb + (n + g) * ROWH + kk + t2);
                bf[j][1] = *reinterpret_cast<const uint32_t*>(Bb + (n + g) * ROWH + kk + t2 + 8);
            }
#pragma unroll
            for (int i = 0; i < MF; i++)
#pragma unroll
                for (int j = 0; j < 4; j++) mma_f16(acc[i][j], af[i], bf[j]);
        }
        const int nk = it + CAS - 1;
        if (nk < nIter) issue(nk % CAS, nk * 32);
        asm volatile("cp.async.commit_group;");
    }

    float* Cf = (float*)Cv;
    __half* Ch = (__half*)Cv;
#pragma unroll
    for (int i = 0; i < MF; i++) {
        const int row0 = bm + wm * (MF * 16) + i * 16 + g;
#pragma unroll
        for (int j = 0; j < 4; j++) {
            const int col = bn + wn * 32 + j * 8 + t2;
            float bz0 = 0.f, bz1 = 0.f;
            if (bias) { bz0 = __ldg(&bias[col]); bz1 = __ldg(&bias[col + 1]); }
            const float v0 = acc[i][j][0] + bz0, v1 = acc[i][j][1] + bz1;
            const float v2 = acc[i][j][2] + bz0, v3 = acc[i][j][3] + bz1;
            if (HOUT == 0) {
                float* C = Cf + (long long)bz * sCz;
                *reinterpret_cast<float2*>(&C[(long long)row0 * N + col]) = make_float2(v0, v1);
                *reinterpret_cast<float2*>(&C[(long long)(row0 + 8) * N + col]) = make_float2(v2, v3);
            } else {
                __half* C = Ch + (long long)bz * sCz;
                *reinterpret_cast<__half2*>(&C[(long long)row0 * N + col]) =
                    __floats2half2_rn(v0, v1);
                *reinterpret_cast<__half2*>(&C[(long long)(row0 + 8) * N + col]) =
                    __floats2half2_rn(v2, v3);
            }
        }
    }
}

// ---------------------------------------------------------------------------
// GRU core: one 256-thread block handles 256*4 elements of (z, B*64 grid).
__device__ __forceinline__
void gru_core(const __half* __restrict__ g, const float* __restrict__ q,
              const float* __restrict__ h0, float* __restrict__ hout,
              __half* __restrict__ h16, long long zslot, int idx, long long Bll)
{
    const int b = idx >> 6;
    const int j = (idx & 63) * 4;
    const __half* gp = g + (long long)b * 768;
    const float* qp  = q + (long long)b * 1536;

    const float2 ir01 = __half22float2(*reinterpret_cast<const __half2*>(gp + j));
    const float2 ir23 = __half22float2(*reinterpret_cast<const __half2*>(gp + j + 2));
    const float2 iz01 = __half22float2(*reinterpret_cast<const __half2*>(gp + 256 + j));
    const float2 iz23 = __half22float2(*reinterpret_cast<const __half2*>(gp + 256 + j + 2));
    const float2 in01 = __half22float2(*reinterpret_cast<const __half2*>(gp + 512 + j));
    const float2 in23 = __half22float2(*reinterpret_cast<const __half2*>(gp + 512 + j + 2));
    const float4 hr = *reinterpret_cast<const float4*>(qp + j);
    const float4 hz = *reinterpret_cast<const float4*>(qp + 256 + j);
    const float4 hn = *reinterpret_cast<const float4*>(qp + 512 + j);
    const float4 hh = *reinterpret_cast<const float4*>(h0 + (long long)b * 256 + j);

    float4 r;
    { const float rr = sigf(ir01.x + hr.x), zz = sigf(iz01.x + hz.x);
      r.x = (1.f - zz) * tanhf(in01.x + rr * hn.x) + zz * hh.x; }
    { const float rr = sigf(ir01.y + hr.y), zz = sigf(iz01.y + hz.y);
      r.y = (1.f - zz) * tanhf(in01.y + rr * hn.y) + zz * hh.y; }
    { const float rr = sigf(ir23.x + hr.z), zz = sigf(iz23.x + hz.z);
      r.z = (1.f - zz) * tanhf(in23.x + rr * hn.z) + zz * hh.z; }
    { const float rr = sigf(ir23.y + hr.w), zz = sigf(iz23.y + hz.w);
      r.w = (1.f - zz) * tanhf(in23.y + rr * hn.w) + zz * hh.w; }

    const long long off = zslot * (Bll * 256) + (long long)b * 256 + j;
    *reinterpret_cast<float4*>(hout + off) = r;
    reinterpret_cast<__half2*>(h16 + off)[0] = __floats2half2_rn(r.x, r.y);
    reinterpret_cast<__half2*>(h16 + off)[1] = __floats2half2_rn(r.z, r.w);
}

// ---------------------------------------------------------------------------
// big_fused: x1-splitK | gh12 | gi2(all cells)  (longest-first ordering)
__global__ __launch_bounds__(256)
void big_fused(const __half* __restrict__ xh, const __half* __restrict__ e1h,
               const __half* __restrict__ hh, const __half* __restrict__ whhh,
               const float* __restrict__ bhh, const __half* __restrict__ w2ph,
               const float* __restrict__ b2p,
               float* __restrict__ xp, float* __restrict__ gh12,
               __half* __restrict__ gi2h,
               const int* __restrict__ cxs, const int* __restrict__ cys,
               int MB, int nX1, int nGH, int B)
{
    const int i = blockIdx.x;
    if (i < nX1) {
        const int bx = i & 1, r = i >> 1;
        gemm_dev<0, 128, 0, 128>(xh, e1h, nullptr, xp, 256, 1024, 4096, 4096,
                                 1024, 1024, (long long)B * 256, nullptr, nullptr,
                                 bx, r % MB, r / MB);
    } else if (i < nX1 + nGH) {
        const int j = i - nX1;
        gemm_dev<0, 128, 0, 128>(hh, whhh, bhh, gh12, 1536, 256, 256, 256,
                                 0, 0, 0, nullptr, nullptr,
                                 j % 12, j / 12, 0);
    } else {
        const int k = i - nX1 - nGH;
        const int bx = k % 6, r = k / 6;
        gemm_dev<1, 128, 1, 128>(xh, w2ph, b2p, gi2h, 768, 64, 64, 64,
                                 0, 0, (long long)B * 768, cxs, cys,
                                 bx, r % MB, r / MB);
    }
}

// ---------------------------------------------------------------------------
// gi1 (64-row M tiles, 192 blocks) ∥ gru-cells (512*Kc blocks)
__global__ __launch_bounds__(256)
void gi1_and_gru_cells(const __half* __restrict__ x1h, const __half* __restrict__ wi1h,
                       const float* __restrict__ bih1, __half* __restrict__ gi1h,
                       const __half* __restrict__ gi2h, const float* __restrict__ gh12,
                       const float* __restrict__ h0,
                       float* __restrict__ hout, __half* __restrict__ h16,
                       int nGi1, int B)
{
    const int i = blockIdx.x;
    if (i < nGi1) {
        gemm_dev<0, 128, 1, 64>(x1h, wi1h, bih1, gi1h, 768, 256, 256, 256,
                                0, 0, 0, nullptr, nullptr,
                                i % 6, i / 6, 0);
    } else {
        const int j = i - nGi1;
        const int z = j >> 9;            // cell 0..Kc-1 (512 blocks per cell)
        const int idx = (j & 511) * 256 + threadIdx.x;
        if (idx < B * 64)
            gru_core(gi2h + (long long)z * B * 768, gh12 + 768, h0,
                     hout, h16, z + 1, idx, (long long)B);
    }
}

// gru layer-1 (z=0)
__global__ void gru_l1_kernel(const __half* __restrict__ gi1h, const float* __restrict__ gh12,
                              const float* __restrict__ h0,
                              float* __restrict__ hout, __half* __restrict__ h16, int B)
{
    const int idx = blockIdx.x * blockDim.x + threadIdx.x;
    if (idx < B * 64)
        gru_core(gi1h, gh12, h0, hout, h16, 0, idx, (long long)B);
}

// merged o GEMM
__global__ __launch_bounds__(256)
void o_gemm(const __half* __restrict__ A,
            const __half* __restrict__ Bw, const __half* __restrict__ Bw2,
            const float* __restrict__ bias, const float* __restrict__ bias2,
            float* __restrict__ C, int B)
{
    const __half* B_ = (blockIdx.z > 0) ? Bw2 : Bw;
    const float* bi  = (blockIdx.z > 0) ? bias2 : bias;
    gemm_dev<0, 64, 0, 128>(A, B_, bi, C, 64, 256, 256, 256,
                            (long long)B * 256, 0, (long long)B * 64,
                            nullptr, nullptr, blockIdx.x, blockIdx.y, blockIdx.z);
}

// ---------------------------------------------------------------------------
__global__ void reduce_x1_kernel(const float* __restrict__ P, const float* __restrict__ bias,
                                 __half* __restrict__ x1, int n4)
{
    const int idx = blockIdx.x * blockDim.x + threadIdx.x;
    if (idx >= n4) return;
    const float4 p0 = *reinterpret_cast<const float4*>(P + (size_t)0 * BSZ * 256 + idx * 4);
    const float4 p1 = *reinterpret_cast<const float4*>(P + (size_t)1 * BSZ * 256 + idx * 4);
    const float4 p2 = *reinterpret_cast<const float4*>(P + (size_t)2 * BSZ * 256 + idx * 4);
    const float4 p3 = *reinterpret_cast<const float4*>(P + (size_t)3 * BSZ * 256 + idx * 4);
    const int j0 = (idx * 4) & 255;
    const float4 b = *reinterpret_cast<const float4*>(bias + j0);
    reinterpret_cast<__half2*>(x1)[idx * 2] =
        __floats2half2_rn(p0.x + p1.x + p2.x + p3.x + b.x,
                          p0.y + p1.y + p2.y + p3.y + b.y);
    reinterpret_cast<__half2*>(x1)[idx * 2 + 1] =
        __floats2half2_rn(p0.z + p1.z + p2.z + p3.z + b.z,
                          p0.w + p1.w + p2.w + p3.w + b.w);
}

// ---------------------------------------------------------------------------
__global__ void assemble_y_kernel(const float* __restrict__ o1, const float* __restrict__ o2,
                                  const int* __restrict__ cmap, float* __restrict__ y, int n4)
{
    const int idx = blockIdx.x * blockDim.x + threadIdx.x;
    if (idx >= n4) return;
    const int b   = idx >> 10;
    const int rem = idx & 1023;
    const int i   = rem >> 4;
    const int j0  = (rem & 15) * 4;
    const float v = __ldg(&o1[b * 64 + i]);
    float4 r = make_float4(v, v, v, v);
    const int k = cmap[(i >> 3) * 8 + (j0 >> 3)];
    if (k >= 0) {
        const int t = (i & 7) * 8 + (j0 & 7);
        const float4 a = *reinterpret_cast<const float4*>(o2 + ((long long)k * BSZ + b) * 64 + t);
        r.x += a.x; r.y += a.y; r.z += a.z; r.w += a.w;
    }
    *reinterpret_cast<float4*>(y + (long long)idx * 4) = r;
}

// ---------------------------------------------------------------------------
extern "C" void kernel_launch(void* const* d_in, const int* in_sizes, int n_in,
                              void* d_out, int out_size)
{
    const float* x    = (const float*)d_in[0];
    const float* h    = (const float*)d_in[1];
    const float* fa   = (const float*)d_in[2];
    const float* e1w  = (const float*)d_in[3];
    const float* e1b  = (const float*)d_in[4];
    const float* wih1 = (const float*)d_in[5];
    const float* whh1 = (const float*)d_in[6];
    const float* bih1 = (const float*)d_in[7];
    const float* bhh1 = (const float*)d_in[8];
    const float* o1w  = (const float*)d_in[9];
    const float* o1b  = (const float*)d_in[10];
    const float* e2w  = (const float*)d_in[11];
    const float* e2b  = (const float*)d_in[12];
    const float* wih2 = (const float*)d_in[13];
    const float* whh2 = (const float*)d_in[14];
    const float* bih2 = (const float*)d_in[15];
    const float* bhh2 = (const float*)d_in[16];
    const float* o2w  = (const float*)d_in[17];
    const float* o2b  = (const float*)d_in[18];
    float* out = (float*)d_out;

    const int B = in_sizes[0] / 4096;                  // 2048
    const long long YOFF = (long long)B * 4096;
    int Kc = (int)(((long long)out_size - YOFF) / ((long long)B * 256)) - 1;
    if (Kc < 0) Kc = 0;
    if (Kc > MAXK) Kc = MAXK;

    __half *p_xh, *p_hh, *p_e1h, *p_wi1h, *p_whhh, *p_o1wh, *p_o2wh,
           *p_x1h, *p_gi1h, *p_gi2h, *p_hh16, *p_w2ph;
    float *p_bhh, *p_xp, *p_gh12, *p_o, *p_b2p;
    int *p_cx, *p_cy, *p_cmap;
    cudaGetSymbolAddress((void**)&p_xh,   d_xh);
    cudaGetSymbolAddress((void**)&p_hh,   d_hh);
    cudaGetSymbolAddress((void**)&p_e1h,  d_e1h);
    cudaGetSymbolAddress((void**)&p_wi1h, d_wi1h);
    cudaGetSymbolAddress((void**)&p_whhh, d_whhh);
    cudaGetSymbolAddress((void**)&p_bhh,  d_bhh);
    cudaGetSymbolAddress((void**)&p_o1wh, d_o1wh);
    cudaGetSymbolAddress((void**)&p_o2wh, d_o2wh);
    cudaGetSymbolAddress((void**)&p_xp,   d_xp);
    cudaGetSymbolAddress((void**)&p_x1h,  d_x1h);
    cudaGetSymbolAddress((void**)&p_gh12, d_gh12);
    cudaGetSymbolAddress((void**)&p_gi1h, d_gi1h);
    cudaGetSymbolAddress((void**)&p_gi2h, d_gi2h);
    cudaGetSymbolAddress((void**)&p_hh16, d_hh16);
    cudaGetSymbolAddress((void**)&p_o,    d_o);
    cudaGetSymbolAddress((void**)&p_w2ph, d_w2ph);
    cudaGetSymbolAddress((void**)&p_b2p,  d_b2p);
    cudaGetSymbolAddress((void**)&p_cx,   d_cx);
    cudaGetSymbolAddress((void**)&p_cy,   d_cy);
    cudaGetSymbolAddress((void**)&p_cmap, d_cmap);

    const int SMB128 = 2 * CAS * (128 * ROWH + 128 * ROWH);  // 61440
    const int SMB96  = 2 * CAS * (64 * ROWH + 128 * ROWH);   // 46080 (gi1 M64/N128)
    const int SMB64  = 2 * CAS * (128 * ROWH + 64 * ROWH);   // 46080
    cudaFuncSetAttribute((const void*)big_fused,         cudaFuncAttributeMaxDynamicSharedMemorySize, SMB128);
    cudaFuncSetAttribute((const void*)gi1_and_gru_cells, cudaFuncAttributeMaxDynamicSharedMemorySize, SMB96);
    cudaFuncSetAttribute((const void*)o_gemm,            cudaFuncAttributeMaxDynamicSharedMemorySize, SMB64);

    float* yh0 = out + YOFF;
    const int MB = B / 128;                       // 16
    const int nPrep = B * 4 + B / 4 + 1024 + 192 + 16 + 16 + 384 + 192 + 1;

    // 1) prep
    prep_kernel<<<nPrep, 256>>>(x, h, e1w, wih1, o1w, o2w, whh1, whh2, bhh1, bhh2,
                                wih2, e2w, e2b, bih2, fa,
                                p_xh, p_hh, p_e1h, p_wi1h, p_o1wh, p_o2wh,
                                p_whhh, p_bhh, p_w2ph, p_b2p,
                                p_cx, p_cy, p_cmap, B);

    // 2) x1-splitK ∥ gh12 ∥ gi2(all cells)
    const int nX1  = 2 * MB * 4;
    const int nGH  = 12 * MB;
    const int nGI2 = 6 * MB * Kc;
    big_fused<<<nX1 + nGH + nGI2, 256, SMB128>>>(
        p_xh, p_e1h, p_hh, p_whhh, p_bhh, p_w2ph, p_b2p,
        p_xp, p_gh12, p_gi2h, p_cx, p_cy, MB, nX1, nGH, B);

    // 3) reduce -> fp16 x1
    reduce_x1_kernel<<<(B * 64 + 255) / 256, 256>>>(p_xp, e1b, p_x1h, B * 64);

    // 4) gi1 (M64 tiles) ∥ gru-cells — gi1 hides under the cell GRU stream
    const int nGi1 = 6 * (B / 64);
    const int nGruC = ((B * 64 + 255) / 256) * Kc;
    gi1_and_gru_cells<<<nGi1 + nGruC, 256, SMB96>>>(
        p_x1h, p_wi1h, bih1, p_gi1h, p_gi2h, p_gh12, h, yh0, p_hh16, nGi1, B);

    // 5) gru layer-1
    gru_l1_kernel<<<(B * 64 + 255) / 256, 256>>>(p_gi1h, p_gh12, h, yh0, p_hh16, B);

    // 6) merged o GEMM
    o_gemm<<<dim3(1, MB, Kc + 1), 256, SMB64>>>(p_hh16, p_o1wh, p_o2wh, o1b, o2b, p_o, B);

    // 7) y = bcast(o1) + scatter(o2)
    assemble_y_kernel<<<(B * 1024 + 255) / 256, 256>>>(p_o, p_o + (long long)B * 64,
                                                       p_cmap, out, B * 1024);
}

// round 12
// speedup vs baseline: 1.4794x; 1.0316x over previous
#include <cuda_runtime.h>
#include <cuda_fp16.h>
#include <cstdint>

// ---------------------------------------------------------------------------
// FocDecoderRNN — R9 structure (fp16 m16n8k16 engine, horizontal fusion).
// R12: fast-math GRU (8 elems/thread), gi1 on 128x64 tiles (192 blocks).
// Closed avenues: GRU-in-GEMM fusion (R4/R10), per-fragment cvt (R7),
// cell chunking (R7), heterogeneous-smem merge (R11).
// ---------------------------------------------------------------------------

#define BSZ  2048
#define MAXK 64

__device__ __half d_xh  [(size_t)BSZ * 4096];
__device__ __half d_hh  [BSZ * 256];
__device__ __half d_e1h [256 * 4096];
__device__ __half d_wi1h[768 * 256];
__device__ __half d_whhh[1536 * 256];
__device__ float  d_bhh [1536];
__device__ __half d_o1wh[64 * 256];
__device__ __half d_o2wh[64 * 256];
__device__ float  d_xp  [4 * BSZ * 256];
__device__ __half d_x1h [BSZ * 256];
__device__ float  d_gh12[(size_t)BSZ * 1536];
__device__ __half d_gi1h[BSZ * 768];
__device__ __half d_gi2h[(size_t)MAXK * BSZ * 768];
__device__ __half d_hh16[(size_t)(MAXK + 1) * BSZ * 256];
__device__ float  d_o   [(size_t)(MAXK + 1) * BSZ * 64];
__device__ __half d_w2ph[768 * 64];
__device__ float  d_b2p [768];
__device__ int    d_cx[MAXK], d_cy[MAXK], d_cmap[64];

// ---------------------------------------------------------------------------
__device__ __forceinline__ void mma_f16(float c[4], const uint32_t a[4], const uint32_t b[2])
{
    asm volatile(
        "mma.sync.aligned.m16n8k16.row.col.f32.f16.f16.f32 "
        "{%0,%1,%2,%3},{%4,%5,%6,%7},{%8,%9},{%0,%1,%2,%3};\n"
        : "+f"(c[0]), "+f"(c[1]), "+f"(c[2]), "+f"(c[3])
        : "r"(a[0]), "r"(a[1]), "r"(a[2]), "r"(a[3]), "r"(b[0]), "r"(b[1]));
}

__device__ __forceinline__ void cp16(uint32_t smem_addr, const void* gptr)
{
    asm volatile("cp.async.cg.shared.global [%0], [%1], 16;"
                 :: "r"(smem_addr), "l"(gptr));
}

__device__ __forceinline__ float sigf(float x)
{
    return __fdividef(1.f, 1.f + __expf(-x));
}
__device__ __forceinline__ float tanhfast(float x)
{
    return 1.f - __fdividef(2.f, __expf(2.f * x) + 1.f);
}

// ---------------------------------------------------------------------------
__device__ __forceinline__ void cvt_job(const float* __restrict__ s, __half* __restrict__ d,
                                        int grp)
{
    const float4 v = reinterpret_cast<const float4*>(s)[grp];
    reinterpret_cast<__half2*>(d)[grp * 2]     = __floats2half2_rn(v.x, v.y);
    reinterpret_cast<__half2*>(d)[grp * 2 + 1] = __floats2half2_rn(v.z, v.w);
}

__global__ void prep_kernel(const float* __restrict__ x,   const float* __restrict__ h,
                            const float* __restrict__ e1w, const float* __restrict__ wih1,
                            const float* __restrict__ o1w, const float* __restrict__ o2w,
                            const float* __restrict__ whh1, const float* __restrict__ whh2,
                            const float* __restrict__ bhh1, const float* __restrict__ bhh2,
                            const float* __restrict__ wih2, const float* __restrict__ e2w,
                            const float* __restrict__ e2b,  const float* __restrict__ bih2,
                            const float* __restrict__ fa,
                            __half* __restrict__ xh,  __half* __restrict__ hh,
                            __half* __restrict__ e1h, __half* __restrict__ wi1h,
                            __half* __restrict__ o1wh, __half* __restrict__ o2wh,
                            __half* __restrict__ whhh, float* __restrict__ bhh,
                            __half* __restrict__ w2ph, float* __restrict__ b2p,
                            int* __restrict__ cx, int* __restrict__ cy, int* __restrict__ cmap,
                            int B)
{
    const int bid = blockIdx.x;
    const int tid = threadIdx.x;
    const int b0 = B * 4;
    const int b1 = b0 + B / 4;
    const int b2 = b1 + 1024;
    const int b3 = b2 + 192;
    const int b4 = b3 + 16;
    const int b5 = b4 + 16;
    const int b6 = b5 + 384;
    const int b7 = b6 + 192;
    if (bid < b0)      { cvt_job(x,    xh,   bid * 256 + tid); }
    else if (bid < b1) { cvt_job(h,    hh,   (bid - b0) * 256 + tid); }
    else if (bid < b2) { cvt_job(e1w,  e1h,  (bid - b1) * 256 + tid); }
    else if (bid < b3) { cvt_job(wih1, wi1h, (bid - b2) * 256 + tid); }
    else if (bid < b4) { cvt_job(o1w,  o1wh, (bid - b3) * 256 + tid); }
    else if (bid < b5) { cvt_job(o2w,  o2wh, (bid - b4) * 256 + tid); }
    else if (bid < b6) {
        const int i = (bid - b5) * 256 + tid;
        const int e = i * 4, row = e >> 8, col = e & 255;
        const float* src = (row < 768) ? (whh1 + row * 256 + col)
                                       : (whh2 + (row - 768) * 256 + col);
        const float4 v = *reinterpret_cast<const float4*>(src);
        reinterpret_cast<__half2*>(whhh)[i * 2]     = __floats2half2_rn(v.x, v.y);
        reinterpret_cast<__half2*>(whhh)[i * 2 + 1] = __floats2half2_rn(v.z, v.w);
        if (i < 1536) bhh[i] = (i < 768) ? bhh1[i] : bhh2[i - 768];
    } else if (bid < b7) {
        const int n = (bid - b6) * 4 + (tid >> 6);
        const int t = tid & 63;
        float s = 0.f;
        for (int c = 0; c < 256; c++)
            s += wih2[n * 256 + c] * e2w[c * 64 + t];
        w2ph[n * 64 + t] = __float2half_rn(s);
        if (t == 0) {
            float sb = 0.f;
            for (int c = 0; c < 256; c++) sb += wih2[n * 256 + c] * e2b[c];
            b2p[n] = bih2[n] + sb;
        }
    } else {
        if (tid == 0) {
            for (int i = 0; i < 64; i++) cmap[i] = -1;
            int k = 0;
            for (int i = 0; i < 8; i++)
                for (int j = 0; j < 8; j++)
                    if (fa[i * 8 + j] > 0.5f) { cx[k] = i; cy[k] = j; cmap[i * 8 + j] = k; k++; }
        }
    }
}

// ---------------------------------------------------------------------------
// FP16 GEMM-NT device core (cp.async 3-stage, K-slab 32, m16n8k16).
#define CAS  3
#define ROWH 40

template<int AMODE, int NT, int HOUT, int MT>
__device__ __forceinline__
void gemm_dev(const __half* __restrict__ A, const __half* __restrict__ Bw,
              const float* __restrict__ bias, void* __restrict__ Cv,
              int N, int K, int lda, int ldb,
              long long sAz, long long sBz, long long sCz,
              const int* __restrict__ cxs, const int* __restrict__ cys,
              int bx, int by, int bz)
{
    constexpr int STG_A = MT * ROWH;
    constexpr int STG_B = NT * ROWH;
    constexpr int WNW   = (NT == 128) ? 4 : 2;
    constexpr int MF    = MT * WNW / 128;

    extern __shared__ __half smh[];
    const uint32_t smBase = (uint32_t)__cvta_generic_to_shared(smh);

    const int bm = by * MT;
    const int bn = bx * NT;
    int cellBase = 0;
    if (AMODE == 1) cellBase = cxs[bz] * 512 + cys[bz] * 8;
    if (AMODE == 0) A += (long long)bz * sAz;
    Bw += (long long)bz * sBz;

    const int tid  = threadIdx.x;
    const int lane = tid & 31;
    const int wid  = tid >> 5;
    const int wm   = wid / WNW;
    const int wn   = wid % WNW;
    const int g    = lane >> 2;
    const int t2   = (lane & 3) * 2;
    const int alr  = (MT == 128) ? (tid >> 1) : (tid >> 2);
    const int alk  = (MT == 128) ? (tid & 1) * 16 : (tid & 3) * 8;
    const int br   = (NT == 128) ? (tid >> 1) : (tid >> 2);
    const int bc   = (NT == 128) ? (tid & 1) * 16 : (tid & 3) * 8;

    float acc[MF][4][4];
#pragma unroll
    for (int i = 0; i < MF; i++)
#pragma unroll
        for (int j = 0; j < 4; j++)
#pragma unroll
            for (int q = 0; q < 4; q++) acc[i][j][q] = 0.f;

    auto issue = [&](int stg, int k0) {
        const __half *ap0, *ap1;
        if (AMODE == 0) {
            ap0 = A + (long long)(bm + alr) * lda + k0 + alk;
            ap1 = ap0 + 8;
        } else {
            const int tt = k0 + alk;
            const __half* base = A + (long long)(bm + alr) * 4096 + cellBase;
            ap0 = base + ((tt >> 3) << 6);
            ap1 = base + (((tt + 8) >> 3) << 6);
        }
        const uint32_t da = smBase + 2u * (stg * STG_A + alr * ROWH + alk);
        cp16(da, ap0);
        if (MT == 128) cp16(da + 16, ap1);
        const __half* bp = Bw + (long long)(bn + br) * ldb + k0 + bc;
        const uint32_t db = smBase + 2u * (CAS * STG_A + stg * STG_B + br * ROWH + bc);
        cp16(db, bp);
        if (NT == 128) cp16(db + 16, bp + 8);
    };

    const int nIter = K >> 5;
#pragma unroll
    for (int s = 0; s < CAS - 1; s++) {
        if (s < nIter) issue(s, s * 32);
        asm volatile("cp.async.commit_group;");
    }

    for (int it = 0; it < nIter; it++) {
        const int cur = it % CAS;
        asm volatile("cp.async.wait_group %0;" :: "n"(CAS - 2));
        __syncthreads();

        const __half* Ab = smh + cur * STG_A;
        const __half* Bb = smh + CAS * STG_A + cur * STG_B;
#pragma unroll
        for (int kk = 0; kk < 32; kk += 16) {
            uint32_t af[MF][4], bf[4][2];
#pragma unroll
            for (int i = 0; i < MF; i++) {
                const int m = wm * (MF * 16) + i * 16;
                af[i][0] = *reinterpret_cast<const uint32_t*>(Ab + (m + g) * ROWH + kk + t2);
                af[i][1] = *reinterpret_cast<const uint32_t*>(Ab + (m + 8 + g) * ROWH + kk + t2);
                af[i][2] = *reinterpret_cast<const uint32_t*>(Ab + (m + g) * ROWH + kk + t2 + 8);
                af[i][3] = *reinterpret_cast<const uint32_t*>(Ab + (m + 8 + g) * ROWH + kk + t2 + 8);
            }
#pragma unroll
            for (int j = 0; j < 4; j++) {
                const int n = wn * 32 + j * 8;
                bf[j][0] = *reinterpret_cast<const uint32_t*>(Bb + (n + g) * ROWH + kk + t2);
                bf[j][1] = *reinterpret_cast<const uint32_t*>(Bb + (n + g) * ROWH + kk + t2 + 8);
            }
#pragma unroll
            for (int i = 0; i < MF; i++)
#pragma unroll
                for (int j = 0; j < 4; j++) mma_f16(acc[i][j], af[i], bf[j]);
        }
        const int nk = it + CAS - 1;
        if (nk < nIter) issue(nk % CAS, nk * 32);
        asm volatile("cp.async.commit_group;");
    }

    float* Cf = (float*)Cv;
    __half* Ch = (__half*)Cv;
#pragma unroll
    for (int i = 0; i < MF; i++) {
        const int row0 = bm + wm * (MF * 16) + i * 16 + g;
#pragma unroll
        for (int j = 0; j < 4; j++) {
            const int col = bn + wn * 32 + j * 8 + t2;
            float bz0 = 0.f, bz1 = 0.f;
            if (bias) { bz0 = __ldg(&bias[col]); bz1 = __ldg(&bias[col + 1]); }
            const float v0 = acc[i][j][0] + bz0, v1 = acc[i][j][1] + bz1;
            const float v2 = acc[i][j][2] + bz0, v3 = acc[i][j][3] + bz1;
            if (HOUT == 0) {
                float* C = Cf + (long long)bz * sCz;
                *reinterpret_cast<float2*>(&C[(long long)row0 * N + col]) = make_float2(v0, v1);
                *reinterpret_cast<float2*>(&C[(long long)(row0 + 8) * N + col]) = make_float2(v2, v3);
            } else {
                __half* C = Ch + (long long)bz * sCz;
                *reinterpret_cast<__half2*>(&C[(long long)row0 * N + col]) =
                    __floats2half2_rn(v0, v1);
                *reinterpret_cast<__half2*>(&C[(long long)(row0 + 8) * N + col]) =
                    __floats2half2_rn(v2, v3);
            }
        }
    }
}

// ---------------------------------------------------------------------------
// big_fused: x1-splitK | gh12 | gi2(all cells)
__global__ __launch_bounds__(256)
void big_fused(const __half* __restrict__ xh, const __half* __restrict__ e1h,
               const __half* __restrict__ hh, const __half* __restrict__ whhh,
               const float* __restrict__ bhh, const __half* __restrict__ w2ph,
               const float* __restrict__ b2p,
               float* __restrict__ xp, float* __restrict__ gh12,
               __half* __restrict__ gi2h,
               const int* __restrict__ cxs, const int* __restrict__ cys,
               int MB, int nX1, int nGH, int B)
{
    const int i = blockIdx.x;
    if (i < nX1) {
        const int bx = i & 1, r = i >> 1;
        gemm_dev<0, 128, 0, 128>(xh, e1h, nullptr, xp, 256, 1024, 4096, 4096,
                                 1024, 1024, (long long)B * 256, nullptr, nullptr,
                                 bx, r % MB, r / MB);
    } else if (i < nX1 + nGH) {
        const int j = i - nX1;
        gemm_dev<0, 128, 0, 128>(hh, whhh, bhh, gh12, 1536, 256, 256, 256,
                                 0, 0, 0, nullptr, nullptr,
                                 j % 12, j / 12, 0);
    } else {
        const int k = i - nX1 - nGH;
        const int bx = k % 6, r = k / 6;
        gemm_dev<1, 128, 1, 128>(xh, w2ph, b2p, gi2h, 768, 64, 64, 64,
                                 0, 0, (long long)B * 768, cxs, cys,
                                 bx, r % MB, r / MB);
    }
}

// gi1 on 128x64 tiles (12 x MB blocks)
__global__ __launch_bounds__(256)
void gi1_kernel(const __half* __restrict__ x1h, const __half* __restrict__ wi1h,
                const float* __restrict__ bih1, __half* __restrict__ gi1h)
{
    gemm_dev<0, 64, 1, 128>(x1h, wi1h, bih1, gi1h, 768, 256, 256, 256,
                            0, 0, 0, nullptr, nullptr,
                            blockIdx.x, blockIdx.y, 0);
}

// merged o GEMM
__global__ __launch_bounds__(256)
void o_gemm(const __half* __restrict__ A,
            const __half* __restrict__ Bw, const __half* __restrict__ Bw2,
            const float* __restrict__ bias, const float* __restrict__ bias2,
            float* __restrict__ C, int B)
{
    const __half* B_ = (blockIdx.z > 0) ? Bw2 : Bw;
    const float* bi  = (blockIdx.z > 0) ? bias2 : bias;
    gemm_dev<0, 64, 0, 128>(A, B_, bi, C, 64, 256, 256, 256,
                            (long long)B * 256, 0, (long long)B * 64,
                            nullptr, nullptr, blockIdx.x, blockIdx.y, blockIdx.z);
}

// ---------------------------------------------------------------------------
__global__ void reduce_x1_kernel(const float* __restrict__ P, const float* __restrict__ bias,
                                 __half* __restrict__ x1, int n4)
{
    const int idx = blockIdx.x * blockDim.x + threadIdx.x;
    if (idx >= n4) return;
    const float4 p0 = *reinterpret_cast<const float4*>(P + (size_t)0 * BSZ * 256 + idx * 4);
    const float4 p1 = *reinterpret_cast<const float4*>(P + (size_t)1 * BSZ * 256 + idx * 4);
    const float4 p2 = *reinterpret_cast<const float4*>(P + (size_t)2 * BSZ * 256 + idx * 4);
    const float4 p3 = *reinterpret_cast<const float4*>(P + (size_t)3 * BSZ * 256 + idx * 4);
    const int j0 = (idx * 4) & 255;
    const float4 b = *reinterpret_cast<const float4*>(bias + j0);
    reinterpret_cast<__half2*>(x1)[idx * 2] =
        __floats2half2_rn(p0.x + p1.x + p2.x + p3.x + b.x,
                          p0.y + p1.y + p2.y + p3.y + b.y);
    reinterpret_cast<__half2*>(x1)[idx * 2 + 1] =
        __floats2half2_rn(p0.z + p1.z + p2.z + p3.z + b.z,
                          p0.w + p1.w + p2.w + p3.w + b.w);
}

// ---------------------------------------------------------------------------
// merged GRU, 8 elements/thread: z=0 -> gi1/gh[0:768]; z>0 -> gi2[z-1]/gh[768:].
__global__ void gru_all_kernel(const __half* __restrict__ gi1, const __half* __restrict__ gi2,
                               const float* __restrict__ gh12, const float* __restrict__ h0,
                               float* __restrict__ hout, __half* __restrict__ h16,
                               int n, long long Bll)
{
    const long long z = blockIdx.z;
    const int idx = blockIdx.x * blockDim.x + threadIdx.x;   // over B*32
    if (idx >= n) return;
    const int b = idx >> 5;
    const int j = (idx & 31) * 8;
    const __half* g = (z == 0) ? (gi1 + (long long)b * 768)
                               : (gi2 + ((z - 1) * Bll + b) * 768);
    const float* q = gh12 + (long long)b * 1536 + (z ? 768 : 0);

    const uint4 irU = *reinterpret_cast<const uint4*>(g + j);
    const uint4 izU = *reinterpret_cast<const uint4*>(g + 256 + j);
    const uint4 inU = *reinterpret_cast<const uint4*>(g + 512 + j);
    const __half2* irh = reinterpret_cast<const __half2*>(&irU);
    const __half2* izh = reinterpret_cast<const __half2*>(&izU);
    const __half2* inh = reinterpret_cast<const __half2*>(&inU);

    const long long obase = z * (Bll * 256) + (long long)b * 256 + j;

#pragma unroll
    for (int hfi = 0; hfi < 2; hfi++) {
        const int jj = j + hfi * 4;
        const float4 hr = *reinterpret_cast<const float4*>(q + jj);
        const float4 hz = *reinterpret_cast<const float4*>(q + 256 + jj);
        const float4 hn = *reinterpret_cast<const float4*>(q + 512 + jj);
        const float4 hh = *reinterpret_cast<const float4*>(h0 + (long long)b * 256 + jj);
        const float2 ir01 = __half22float2(irh[hfi * 2]);
        const float2 ir23 = __half22float2(irh[hfi * 2 + 1]);
        const float2 iz01 = __half22float2(izh[hfi * 2]);
        const float2 iz23 = __half22float2(izh[hfi * 2 + 1]);
        const float2 in01 = __half22float2(inh[hfi * 2]);
        const float2 in23 = __half22float2(inh[hfi * 2 + 1]);

        float4 r;
        { const float rr = sigf(ir01.x + hr.x), zz = sigf(iz01.x + hz.x);
          r.x = (1.f - zz) * tanhfast(in01.x + rr * hn.x) + zz * hh.x; }
        { const float rr = sigf(ir01.y + hr.y), zz = sigf(iz01.y + hz.y);
          r.y = (1.f - zz) * tanhfast(in01.y + rr * hn.y) + zz * hh.y; }
        { const float rr = sigf(ir23.x + hr.z), zz = sigf(iz23.x + hz.z);
          r.z = (1.f - zz) * tanhfast(in23.x + rr * hn.z) + zz * hh.z; }
        { const float rr = sigf(ir23.y + hr.w), zz = sigf(iz23.y + hz.w);
          r.w = (1.f - zz) * tanhfast(in23.y + rr * hn.w) + zz * hh.w; }

        *reinterpret_cast<float4*>(hout + obase + hfi * 4) = r;
        reinterpret_cast<__half2*>(h16 + obase + hfi * 4)[0] = __floats2half2_rn(r.x, r.y);
        reinterpret_cast<__half2*>(h16 + obase + hfi * 4)[1] = __floats2half2_rn(r.z, r.w);
    }
}

// ---------------------------------------------------------------------------
__global__ void assemble_y_kernel(const float* __restrict__ o1, const float* __restrict__ o2,
                                  const int* __restrict__ cmap, float* __restrict__ y, int n4)
{
    const int idx = blockIdx.x * blockDim.x + threadIdx.x;
    if (idx >= n4) return;
    const int b   = idx >> 10;
    const int rem = idx & 1023;
    const int i   = rem >> 4;
    const int j0  = (rem & 15) * 4;
    const float v = __ldg(&o1[b * 64 + i]);
    float4 r = make_float4(v, v, v, v);
    const int k = cmap[(i >> 3) * 8 + (j0 >> 3)];
    if (k >= 0) {
        const int t = (i & 7) * 8 + (j0 & 7);
        const float4 a = *reinterpret_cast<const float4*>(o2 + ((long long)k * BSZ + b) * 64 + t);
        r.x += a.x; r.y += a.y; r.z += a.z; r.w += a.w;
    }
    *reinterpret_cast<float4*>(y + (long long)idx * 4) = r;
}

// ---------------------------------------------------------------------------
extern "C" void kernel_launch(void* const* d_in, const int* in_sizes, int n_in,
                              void* d_out, int out_size)
{
    const float* x    = (const float*)d_in[0];
    const float* h    = (const float*)d_in[1];
    const float* fa   = (const float*)d_in[2];
    const float* e1w  = (const float*)d_in[3];
    const float* e1b  = (const float*)d_in[4];
    const float* wih1 = (const float*)d_in[5];
    const float* whh1 = (const float*)d_in[6];
    const float* bih1 = (const float*)d_in[7];
    const float* bhh1 = (const float*)d_in[8];
    const float* o1w  = (const float*)d_in[9];
    const float* o1b  = (const float*)d_in[10];
    const float* e2w  = (const float*)d_in[11];
    const float* e2b  = (const float*)d_in[12];
    const float* wih2 = (const float*)d_in[13];
    const float* whh2 = (const float*)d_in[14];
    const float* bih2 = (const float*)d_in[15];
    const float* bhh2 = (const float*)d_in[16];
    const float* o2w  = (const float*)d_in[17];
    const float* o2b  = (const float*)d_in[18];
    float* out = (float*)d_out;

    const int B = in_sizes[0] / 4096;                  // 2048
    const long long YOFF = (long long)B * 4096;
    int Kc = (int)(((long long)out_size - YOFF) / ((long long)B * 256)) - 1;
    if (Kc < 0) Kc = 0;
    if (Kc > MAXK) Kc = MAXK;

    __half *p_xh, *p_hh, *p_e1h, *p_wi1h, *p_whhh, *p_o1wh, *p_o2wh,
           *p_x1h, *p_gi1h, *p_gi2h, *p_hh16, *p_w2ph;
    float *p_bhh, *p_xp, *p_gh12, *p_o, *p_b2p;
    int *p_cx, *p_cy, *p_cmap;
    cudaGetSymbolAddress((void**)&p_xh,   d_xh);
    cudaGetSymbolAddress((void**)&p_hh,   d_hh);
    cudaGetSymbolAddress((void**)&p_e1h,  d_e1h);
    cudaGetSymbolAddress((void**)&p_wi1h, d_wi1h);
    cudaGetSymbolAddress((void**)&p_whhh, d_whhh);
    cudaGetSymbolAddress((void**)&p_bhh,  d_bhh);
    cudaGetSymbolAddress((void**)&p_o1wh, d_o1wh);
    cudaGetSymbolAddress((void**)&p_o2wh, d_o2wh);
    cudaGetSymbolAddress((void**)&p_xp,   d_xp);
    cudaGetSymbolAddress((void**)&p_x1h,  d_x1h);
    cudaGetSymbolAddress((void**)&p_gh12, d_gh12);
    cudaGetSymbolAddress((void**)&p_gi1h, d_gi1h);
    cudaGetSymbolAddress((void**)&p_gi2h, d_gi2h);
    cudaGetSymbolAddress((void**)&p_hh16, d_hh16);
    cudaGetSymbolAddress((void**)&p_o,    d_o);
    cudaGetSymbolAddress((void**)&p_w2ph, d_w2ph);
    cudaGetSymbolAddress((void**)&p_b2p,  d_b2p);
    cudaGetSymbolAddress((void**)&p_cx,   d_cx);
    cudaGetSymbolAddress((void**)&p_cy,   d_cy);
    cudaGetSymbolAddress((void**)&p_cmap, d_cmap);

    const int SMB128 = 2 * CAS * (128 * ROWH + 128 * ROWH);  // 61440
    const int SMB64  = 2 * CAS * (128 * ROWH + 64 * ROWH);   // 46080
    cudaFuncSetAttribute((const void*)big_fused,  cudaFuncAttributeMaxDynamicSharedMemorySize, SMB128);
    cudaFuncSetAttribute((const void*)gi1_kernel, cudaFuncAttributeMaxDynamicSharedMemorySize, SMB64);
    cudaFuncSetAttribute((const void*)o_gemm,     cudaFuncAttributeMaxDynamicSharedMemorySize, SMB64);

    float* yh0 = out + YOFF;
    const int MB = B / 128;                       // 16
    const int nPrep = B * 4 + B / 4 + 1024 + 192 + 16 + 16 + 384 + 192 + 1;

    // 1) prep
    prep_kernel<<<nPrep, 256>>>(x, h, e1w, wih1, o1w, o2w, whh1, whh2, bhh1, bhh2,
                                wih2, e2w, e2b, bih2, fa,
                                p_xh, p_hh, p_e1h, p_wi1h, p_o1wh, p_o2wh,
                                p_whhh, p_bhh, p_w2ph, p_b2p,
                                p_cx, p_cy, p_cmap, B);

    // 2) x1-splitK ∥ gh12 ∥ gi2(all cells)
    const int nX1  = 2 * MB * 4;
    const int nGH  = 12 * MB;
    const int nGI2 = 6 * MB * Kc;
    big_fused<<<nX1 + nGH + nGI2, 256, SMB128>>>(
        p_xh, p_e1h, p_hh, p_whhh, p_bhh, p_w2ph, p_b2p,
        p_xp, p_gh12, p_gi2h, p_cx, p_cy, MB, nX1, nGH, B);

    // 3) reduce -> fp16 x1
    reduce_x1_kernel<<<(B * 64 + 255) / 256, 256>>>(p_xp, e1b, p_x1h, B * 64);

    // 4) gi1 (128x64 tiles, 192 blocks)
    gi1_kernel<<<dim3(12, MB), 256, SMB64>>>(p_x1h, p_wi1h, bih1, p_gi1h);

    // 5) all GRUs (8 elems/thread)
    gru_all_kernel<<<dim3((B * 32 + 255) / 256, 1, Kc + 1), 256>>>(
        p_gi1h, p_gi2h, p_gh12, h, yh0, p_hh16, B * 32, (long long)B);

    // 6) merged o GEMM
    o_gemm<<<dim3(1, MB, Kc + 1), 256, SMB64>>>(p_hh16, p_o1wh, p_o2wh, o1b, o2b, p_o, B);

    // 7) y = bcast(o1) + scatter(o2)
    assemble_y_kernel<<<(B * 1024 + 255) / 256, 256>>>(p_o, p_o + (long long)B * 64,
                                                       p_cmap, out, B * 1024);
}

// round 13
// speedup vs baseline: 1.5670x; 1.0592x over previous
#include <cuda_runtime.h>
#include <cuda_fp16.h>
#include <cstdint>

// ---------------------------------------------------------------------------
// FocDecoderRNN — R12 base + multi-cell gi2 blocks (B-tile reuse, filled
// pipeline). Closed avenues: GRU-in-GEMM fusion, per-fragment cvt, cell
// chunking across launches, heterogeneous-smem merge.
// ---------------------------------------------------------------------------

#define BSZ  2048
#define MAXK 64
#define ZCH  4        // cells per gi2 block

__device__ __half d_xh  [(size_t)BSZ * 4096];
__device__ __half d_hh  [BSZ * 256];
__device__ __half d_e1h [256 * 4096];
__device__ __half d_wi1h[768 * 256];
__device__ __half d_whhh[1536 * 256];
__device__ float  d_bhh [1536];
__device__ __half d_o1wh[64 * 256];
__device__ __half d_o2wh[64 * 256];
__device__ float  d_xp  [4 * BSZ * 256];
__device__ __half d_x1h [BSZ * 256];
__device__ float  d_gh12[(size_t)BSZ * 1536];
__device__ __half d_gi1h[BSZ * 768];
__device__ __half d_gi2h[(size_t)MAXK * BSZ * 768];
__device__ __half d_hh16[(size_t)(MAXK + 1) * BSZ * 256];
__device__ float  d_o   [(size_t)(MAXK + 1) * BSZ * 64];
__device__ __half d_w2ph[768 * 64];
__device__ float  d_b2p [768];
__device__ int    d_cx[MAXK], d_cy[MAXK], d_cmap[64];

// ---------------------------------------------------------------------------
__device__ __forceinline__ void mma_f16(float c[4], const uint32_t a[4], const uint32_t b[2])
{
    asm volatile(
        "mma.sync.aligned.m16n8k16.row.col.f32.f16.f16.f32 "
        "{%0,%1,%2,%3},{%4,%5,%6,%7},{%8,%9},{%0,%1,%2,%3};\n"
        : "+f"(c[0]), "+f"(c[1]), "+f"(c[2]), "+f"(c[3])
        : "r"(a[0]), "r"(a[1]), "r"(a[2]), "r"(a[3]), "r"(b[0]), "r"(b[1]));
}

__device__ __forceinline__ void cp16(uint32_t smem_addr, const void* gptr)
{
    asm volatile("cp.async.cg.shared.global [%0], [%1], 16;"
                 :: "r"(smem_addr), "l"(gptr));
}

__device__ __forceinline__ float sigf(float x)
{
    return __fdividef(1.f, 1.f + __expf(-x));
}
__device__ __forceinline__ float tanhfast(float x)
{
    return 1.f - __fdividef(2.f, __expf(2.f * x) + 1.f);
}

// ---------------------------------------------------------------------------
__device__ __forceinline__ void cvt_job(const float* __restrict__ s, __half* __restrict__ d,
                                        int grp)
{
    const float4 v = reinterpret_cast<const float4*>(s)[grp];
    reinterpret_cast<__half2*>(d)[grp * 2]     = __floats2half2_rn(v.x, v.y);
    reinterpret_cast<__half2*>(d)[grp * 2 + 1] = __floats2half2_rn(v.z, v.w);
}

__global__ void prep_kernel(const float* __restrict__ x,   const float* __restrict__ h,
                            const float* __restrict__ e1w, const float* __restrict__ wih1,
                            const float* __restrict__ o1w, const float* __restrict__ o2w,
                            const float* __restrict__ whh1, const float* __restrict__ whh2,
                            const float* __restrict__ bhh1, const float* __restrict__ bhh2,
                            const float* __restrict__ wih2, const float* __restrict__ e2w,
                            const float* __restrict__ e2b,  const float* __restrict__ bih2,
                            const float* __restrict__ fa,
                            __half* __restrict__ xh,  __half* __restrict__ hh,
                            __half* __restrict__ e1h, __half* __restrict__ wi1h,
                            __half* __restrict__ o1wh, __half* __restrict__ o2wh,
                            __half* __restrict__ whhh, float* __restrict__ bhh,
                            __half* __restrict__ w2ph, float* __restrict__ b2p,
                            int* __restrict__ cx, int* __restrict__ cy, int* __restrict__ cmap,
                            int B)
{
    const int bid = blockIdx.x;
    const int tid = threadIdx.x;
    const int b0 = B * 4;
    const int b1 = b0 + B / 4;
    const int b2 = b1 + 1024;
    const int b3 = b2 + 192;
    const int b4 = b3 + 16;
    const int b5 = b4 + 16;
    const int b6 = b5 + 384;
    const int b7 = b6 + 192;
    if (bid < b0)      { cvt_job(x,    xh,   bid * 256 + tid); }
    else if (bid < b1) { cvt_job(h,    hh,   (bid - b0) * 256 + tid); }
    else if (bid < b2) { cvt_job(e1w,  e1h,  (bid - b1) * 256 + tid); }
    else if (bid < b3) { cvt_job(wih1, wi1h, (bid - b2) * 256 + tid); }
    else if (bid < b4) { cvt_job(o1w,  o1wh, (bid - b3) * 256 + tid); }
    else if (bid < b5) { cvt_job(o2w,  o2wh, (bid - b4) * 256 + tid); }
    else if (bid < b6) {
        const int i = (bid - b5) * 256 + tid;
        const int e = i * 4, row = e >> 8, col = e & 255;
        const float* src = (row < 768) ? (whh1 + row * 256 + col)
                                       : (whh2 + (row - 768) * 256 + col);
        const float4 v = *reinterpret_cast<const float4*>(src);
        reinterpret_cast<__half2*>(whhh)[i * 2]     = __floats2half2_rn(v.x, v.y);
        reinterpret_cast<__half2*>(whhh)[i * 2 + 1] = __floats2half2_rn(v.z, v.w);
        if (i < 1536) bhh[i] = (i < 768) ? bhh1[i] : bhh2[i - 768];
    } else if (bid < b7) {
        const int n = (bid - b6) * 4 + (tid >> 6);
        const int t = tid & 63;
        float s = 0.f;
        for (int c = 0; c < 256; c++)
            s += wih2[n * 256 + c] * e2w[c * 64 + t];
        w2ph[n * 64 + t] = __float2half_rn(s);
        if (t == 0) {
            float sb = 0.f;
            for (int c = 0; c < 256; c++) sb += wih2[n * 256 + c] * e2b[c];
            b2p[n] = bih2[n] + sb;
        }
    } else {
        if (tid == 0) {
            for (int i = 0; i < 64; i++) cmap[i] = -1;
            int k = 0;
            for (int i = 0; i < 8; i++)
                for (int j = 0; j < 8; j++)
                    if (fa[i * 8 + j] > 0.5f) { cx[k] = i; cy[k] = j; cmap[i * 8 + j] = k; k++; }
        }
    }
}

// ---------------------------------------------------------------------------
// FP16 GEMM-NT device core (cp.async 3-stage, K-slab 32, m16n8k16).
#define CAS  3
#define ROWH 40

template<int AMODE, int NT, int HOUT, int MT>
__device__ __forceinline__
void gemm_dev(const __half* __restrict__ A, const __half* __restrict__ Bw,
              const float* __restrict__ bias, void* __restrict__ Cv,
              int N, int K, int lda, int ldb,
              long long sAz, long long sBz, long long sCz,
              const int* __restrict__ cxs, const int* __restrict__ cys,
              int bx, int by, int bz)
{
    constexpr int STG_A = MT * ROWH;
    constexpr int STG_B = NT * ROWH;
    constexpr int WNW   = (NT == 128) ? 4 : 2;
    constexpr int MF    = MT * WNW / 128;

    extern __shared__ __half smh[];
    const uint32_t smBase = (uint32_t)__cvta_generic_to_shared(smh);

    const int bm = by * MT;
    const int bn = bx * NT;
    int cellBase = 0;
    if (AMODE == 1) cellBase = cxs[bz] * 512 + cys[bz] * 8;
    if (AMODE == 0) A += (long long)bz * sAz;
    Bw += (long long)bz * sBz;

    const int tid  = threadIdx.x;
    const int lane = tid & 31;
    const int wid  = tid >> 5;
    const int wm   = wid / WNW;
    const int wn   = wid % WNW;
    const int g    = lane >> 2;
    const int t2   = (lane & 3) * 2;
    const int alr  = (MT == 128) ? (tid >> 1) : (tid >> 2);
    const int alk  = (MT == 128) ? (tid & 1) * 16 : (tid & 3) * 8;
    const int br   = (NT == 128) ? (tid >> 1) : (tid >> 2);
    const int bc   = (NT == 128) ? (tid & 1) * 16 : (tid & 3) * 8;

    float acc[MF][4][4];
#pragma unroll
    for (int i = 0; i < MF; i++)
#pragma unroll
        for (int j = 0; j < 4; j++)
#pragma unroll
            for (int q = 0; q < 4; q++) acc[i][j][q] = 0.f;

    auto issue = [&](int stg, int k0) {
        const __half *ap0, *ap1;
        if (AMODE == 0) {
            ap0 = A + (long long)(bm + alr) * lda + k0 + alk;
            ap1 = ap0 + 8;
        } else {
            const int tt = k0 + alk;
            const __half* base = A + (long long)(bm + alr) * 4096 + cellBase;
            ap0 = base + ((tt >> 3) << 6);
            ap1 = base + (((tt + 8) >> 3) << 6);
        }
        const uint32_t da = smBase + 2u * (stg * STG_A + alr * ROWH + alk);
        cp16(da, ap0);
        if (MT == 128) cp16(da + 16, ap1);
        const __half* bp = Bw + (long long)(bn + br) * ldb + k0 + bc;
        const uint32_t db = smBase + 2u * (CAS * STG_A + stg * STG_B + br * ROWH + bc);
        cp16(db, bp);
        if (NT == 128) cp16(db + 16, bp + 8);
    };

    const int nIter = K >> 5;
#pragma unroll
    for (int s = 0; s < CAS - 1; s++) {
        if (s < nIter) issue(s, s * 32);
        asm volatile("cp.async.commit_group;");
    }

    for (int it = 0; it < nIter; it++) {
        const int cur = it % CAS;
        asm volatile("cp.async.wait_group %0;" :: "n"(CAS - 2));
        __syncthreads();

        const __half* Ab = smh + cur * STG_A;
        const __half* Bb = smh + CAS * STG_A + cur * STG_B;
#pragma unroll
        for (int kk = 0; kk < 32; kk += 16) {
            uint32_t af[MF][4], bf[4][2];
#pragma unroll
            for (int i = 0; i < MF; i++) {
                const int m = wm * (MF * 16) + i * 16;
                af[i][0] = *reinterpret_cast<const uint32_t*>(Ab + (m + g) * ROWH + kk + t2);
                af[i][1] = *reinterpret_cast<const uint32_t*>(Ab + (m + 8 + g) * ROWH + kk + t2);
                af[i][2] = *reinterpret_cast<const uint32_t*>(Ab + (m + g) * ROWH + kk + t2 + 8);
                af[i][3] = *reinterpret_cast<const uint32_t*>(Ab + (m + 8 + g) * ROWH + kk + t2 + 8);
            }
#pragma unroll
            for (int j = 0; j < 4; j++) {
                const int n = wn * 32 + j * 8;
                bf[j][0] = *reinterpret_cast<const uint32_t*>(Bb + (n + g) * ROWH + kk + t2);
                bf[j][1] = *reinterpret_cast<const uint32_t*>(Bb + (n + g) * ROWH + kk + t2 + 8);
            }
#pragma unroll
            for (int i = 0; i < MF; i++)
#pragma unroll
                for (int j = 0; j < 4; j++) mma_f16(acc[i][j], af[i], bf[j]);
        }
        const int nk = it + CAS - 1;
        if (nk < nIter) issue(nk % CAS, nk * 32);
        asm volatile("cp.async.commit_group;");
    }

    float* Cf = (float*)Cv;
    __half* Ch = (__half*)Cv;
#pragma unroll
    for (int i = 0; i < MF; i++) {
        const int row0 = bm + wm * (MF * 16) + i * 16 + g;
#pragma unroll
        for (int j = 0; j < 4; j++) {
            const int col = bn + wn * 32 + j * 8 + t2;
            float bz0 = 0.f, bz1 = 0.f;
            if (bias) { bz0 = __ldg(&bias[col]); bz1 = __ldg(&bias[col + 1]); }
            const float v0 = acc[i][j][0] + bz0, v1 = acc[i][j][1] + bz1;
            const float v2 = acc[i][j][2] + bz0, v3 = acc[i][j][3] + bz1;
            if (HOUT == 0) {
                float* C = Cf + (long long)bz * sCz;
                *reinterpret_cast<float2*>(&C[(long long)row0 * N + col]) = make_float2(v0, v1);
                *reinterpret_cast<float2*>(&C[(long long)(row0 + 8) * N + col]) = make_float2(v2, v3);
            } else {
                __half* C = Ch + (long long)bz * sCz;
                *reinterpret_cast<__half2*>(&C[(long long)row0 * N + col]) =
                    __floats2half2_rn(v0, v1);
                *reinterpret_cast<__half2*>(&C[(long long)(row0 + 8) * N + col]) =
                    __floats2half2_rn(v2, v3);
            }
        }
    }
}

// ---------------------------------------------------------------------------
// gi2 multi-cell: one 128x128 tile position, ZCH cells per block.
// B (w2ph, K=64) loaded once; A (gathered patches) double-buffered across
// cells so cell z+1's loads overlap cell z's mma+store.
#define ROW2 72   // 64 + 8 pad halves; (4g+t)%32 all-distinct -> bank-clean

__device__ __forceinline__
void gi2_multi(const __half* __restrict__ xh, const __half* __restrict__ w2ph,
               const float* __restrict__ b2p, __half* __restrict__ gi2h,
               const int* __restrict__ cxs, const int* __restrict__ cys,
               int bx, int by, int z0, int zn, int B)
{
    extern __shared__ __half smh[];
    const uint32_t smBase = (uint32_t)__cvta_generic_to_shared(smh);
    const uint32_t bOff = 2 * 128 * ROW2;          // B after 2 A buffers

    const int bm = by * 128;
    const int bn = bx * 128;

    const int tid  = threadIdx.x;
    const int lane = tid & 31;
    const int wid  = tid >> 5;
    const int wm   = wid >> 2;        // 0..1
    const int wn   = wid & 3;         // 0..3
    const int g    = lane >> 2;
    const int t2   = (lane & 3) * 2;
    const int lr   = tid >> 1;        // 0..127
    const int lc   = (tid & 1) * 32;  // 0 / 32 halves

    auto issueA = [&](int buf, int zi) {
        const int cellBase = cxs[z0 + zi] * 512 + cys[z0 + zi] * 8;
        const __half* base = xh + (long long)(bm + lr) * 4096 + cellBase + (lc >> 3) * 64;
        const uint32_t da = smBase + 2u * ((buf * 128 + lr) * ROW2 + lc);
#pragma unroll
        for (int q = 0; q < 4; q++)
            cp16(da + q * 16, base + q * 64);     // each cp16 = one 8-half group
    };

    // B once (row-major, ldb=64, contiguous)
    {
        const __half* bp = w2ph + (long long)(bn + lr) * 64 + lc;
        const uint32_t db = smBase + 2u * (bOff + lr * ROW2 + lc);
#pragma unroll
        for (int q = 0; q < 4; q++)
            cp16(db + q * 16, bp + q * 8);
    }
    issueA(0, 0);
    asm volatile("cp.async.commit_group;");        // g0 = B + A0

    // bias preload (columns fixed across cells)
    float bzv[4][2];
#pragma unroll
    for (int j = 0; j < 4; j++) {
        const int col = bn + wn * 32 + j * 8 + t2;
        bzv[j][0] = __ldg(&b2p[col]);
        bzv[j][1] = __ldg(&b2p[col + 1]);
    }

    const __half* Bs = smh + bOff;
    for (int zi = 0; zi < zn; zi++) {
        if (zi + 1 < zn) issueA((zi + 1) & 1, zi + 1);
        asm volatile("cp.async.commit_group;");
        asm volatile("cp.async.wait_group 1;");    // A(zi) + B guaranteed done
        __syncthreads();

        const __half* Ab = smh + ((zi & 1) * 128) * ROW2;
        float acc[4][4][4];
#pragma unroll
        for (int i = 0; i < 4; i++)
#pragma unroll
            for (int j = 0; j < 4; j++)
#pragma unroll
                for (int q = 0; q < 4; q++) acc[i][j][q] = 0.f;

#pragma unroll
        for (int kk = 0; kk < 64; kk += 16) {
            uint32_t af[4][4], bf[4][2];
#pragma unroll
            for (int i = 0; i < 4; i++) {
                const int m = wm * 64 + i * 16;
                af[i][0] = *reinterpret_cast<const uint32_t*>(Ab + (m + g) * ROW2 + kk + t2);
                af[i][1] = *reinterpret_cast<const uint32_t*>(Ab + (m + 8 + g) * ROW2 + kk + t2);
                af[i][2] = *reinterpret_cast<const uint32_t*>(Ab + (m + g) * ROW2 + kk + t2 + 8);
                af[i][3] = *reinterpret_cast<const uint32_t*>(Ab + (m + 8 + g) * ROW2 + kk + t2 + 8);
            }
#pragma unroll
            for (int j = 0; j < 4; j++) {
                const int n = wn * 32 + j * 8;
                bf[j][0] = *reinterpret_cast<const uint32_t*>(Bs + (n + g) * ROW2 + kk + t2);
                bf[j][1] = *reinterpret_cast<const uint32_t*>(Bs + (n + g) * ROW2 + kk + t2 + 8);
            }
#pragma unroll
            for (int i = 0; i < 4; i++)
#pragma unroll
                for (int j = 0; j < 4; j++) mma_f16(acc[i][j], af[i], bf[j]);
        }

        // store cell zi (fp16, bias fused)
        __half* C = gi2h + (long long)(z0 + zi) * B * 768;
#pragma unroll
        for (int i = 0; i < 4; i++) {
            const int row0 = bm + wm * 64 + i * 16 + g;
#pragma unroll
            for (int j = 0; j < 4; j++) {
                const int col = bn + wn * 32 + j * 8 + t2;
                *reinterpret_cast<__half2*>(&C[(long long)row0 * 768 + col]) =
                    __floats2half2_rn(acc[i][j][0] + bzv[j][0], acc[i][j][1] + bzv[j][1]);
                *reinterpret_cast<__half2*>(&C[(long long)(row0 + 8) * 768 + col]) =
                    __floats2half2_rn(acc[i][j][2] + bzv[j][0], acc[i][j][3] + bzv[j][1]);
            }
        }
        __syncthreads();   // protect A buffer reuse before next issue
    }
}

// ---------------------------------------------------------------------------
// big_fused: x1-splitK | gh12 | gi2-multi(all cells)
__global__ __launch_bounds__(256)
void big_fused(const __half* __restrict__ xh, const __half* __restrict__ e1h,
               const __half* __restrict__ hh, const __half* __restrict__ whhh,
               const float* __restrict__ bhh, const __half* __restrict__ w2ph,
               const float* __restrict__ b2p,
               float* __restrict__ xp, float* __restrict__ gh12,
               __half* __restrict__ gi2h,
               const int* __restrict__ cxs, const int* __restrict__ cys,
               int MB, int nX1, int nGH, int Kc, int B)
{
    const int i = blockIdx.x;
    if (i < nX1) {
        const int bx = i & 1, r = i >> 1;
        gemm_dev<0, 128, 0, 128>(xh, e1h, nullptr, xp, 256, 1024, 4096, 4096,
                                 1024, 1024, (long long)B * 256, nullptr, nullptr,
                                 bx, r % MB, r / MB);
    } else if (i < nX1 + nGH) {
        const int j = i - nX1;
        gemm_dev<0, 128, 0, 128>(hh, whhh, bhh, gh12, 1536, 256, 256, 256,
                                 0, 0, 0, nullptr, nullptr,
                                 j % 12, j / 12, 0);
    } else {
        const int k = i - nX1 - nGH;
        const int bx = k % 6, r = k / 6;
        const int by = r % MB, zg = r / MB;
        const int z0 = zg * ZCH;
        const int zn = (Kc - z0 < ZCH) ? (Kc - z0) : ZCH;
        gi2_multi(xh, w2ph, b2p, gi2h, cxs, cys, bx, by, z0, zn, B);
    }
}

// gi1 on 128x64 tiles (12 x MB blocks)
__global__ __launch_bounds__(256)
void gi1_kernel(const __half* __restrict__ x1h, const __half* __restrict__ wi1h,
                const float* __restrict__ bih1, __half* __restrict__ gi1h)
{
    gemm_dev<0, 64, 1, 128>(x1h, wi1h, bih1, gi1h, 768, 256, 256, 256,
                            0, 0, 0, nullptr, nullptr,
                            blockIdx.x, blockIdx.y, 0);
}

// merged o GEMM
__global__ __launch_bounds__(256)
void o_gemm(const __half* __restrict__ A,
            const __half* __restrict__ Bw, const __half* __restrict__ Bw2,
            const float* __restrict__ bias, const float* __restrict__ bias2,
            float* __restrict__ C, int B)
{
    const __half* B_ = (blockIdx.z > 0) ? Bw2 : Bw;
    const float* bi  = (blockIdx.z > 0) ? bias2 : bias;
    gemm_dev<0, 64, 0, 128>(A, B_, bi, C, 64, 256, 256, 256,
                            (long long)B * 256, 0, (long long)B * 64,
                            nullptr, nullptr, blockIdx.x, blockIdx.y, blockIdx.z);
}

// ---------------------------------------------------------------------------
__global__ void reduce_x1_kernel(const float* __restrict__ P, const float* __restrict__ bias,
                                 __half* __restrict__ x1, int n4)
{
    const int idx = blockIdx.x * blockDim.x + threadIdx.x;
    if (idx >= n4) return;
    const float4 p0 = *reinterpret_cast<const float4*>(P + (size_t)0 * BSZ * 256 + idx * 4);
    const float4 p1 = *reinterpret_cast<const float4*>(P + (size_t)1 * BSZ * 256 + idx * 4);
    const float4 p2 = *reinterpret_cast<const float4*>(P + (size_t)2 * BSZ * 256 + idx * 4);
    const float4 p3 = *reinterpret_cast<const float4*>(P + (size_t)3 * BSZ * 256 + idx * 4);
    const int j0 = (idx * 4) & 255;
    const float4 b = *reinterpret_cast<const float4*>(bias + j0);
    reinterpret_cast<__half2*>(x1)[idx * 2] =
        __floats2half2_rn(p0.x + p1.x + p2.x + p3.x + b.x,
                          p0.y + p1.y + p2.y + p3.y + b.y);
    reinterpret_cast<__half2*>(x1)[idx * 2 + 1] =
        __floats2half2_rn(p0.z + p1.z + p2.z + p3.z + b.z,
                          p0.w + p1.w + p2.w + p3.w + b.w);
}

// ---------------------------------------------------------------------------
// merged GRU, 8 elements/thread
__global__ void gru_all_kernel(const __half* __restrict__ gi1, const __half* __restrict__ gi2,
                               const float* __restrict__ gh12, const float* __restrict__ h0,
                               float* __restrict__ hout, __half* __restrict__ h16,
                               int n, long long Bll)
{
    const long long z = blockIdx.z;
    const int idx = blockIdx.x * blockDim.x + threadIdx.x;
    if (idx >= n) return;
    const int b = idx >> 5;
    const int j = (idx & 31) * 8;
    const __half* g = (z == 0) ? (gi1 + (long long)b * 768)
                               : (gi2 + ((z - 1) * Bll + b) * 768);
    const float* q = gh12 + (long long)b * 1536 + (z ? 768 : 0);

    const uint4 irU = *reinterpret_cast<const uint4*>(g + j);
    const uint4 izU = *reinterpret_cast<const uint4*>(g + 256 + j);
    const uint4 inU = *reinterpret_cast<const uint4*>(g + 512 + j);
    const __half2* irh = reinterpret_cast<const __half2*>(&irU);
    const __half2* izh = reinterpret_cast<const __half2*>(&izU);
    const __half2* inh = reinterpret_cast<const __half2*>(&inU);

    const long long obase = z * (Bll * 256) + (long long)b * 256 + j;

#pragma unroll
    for (int hfi = 0; hfi < 2; hfi++) {
        const int jj = j + hfi * 4;
        const float4 hr = *reinterpret_cast<const float4*>(q + jj);
        const float4 hz = *reinterpret_cast<const float4*>(q + 256 + jj);
        const float4 hn = *reinterpret_cast<const float4*>(q + 512 + jj);
        const float4 hh = *reinterpret_cast<const float4*>(h0 + (long long)b * 256 + jj);
        const float2 ir01 = __half22float2(irh[hfi * 2]);
        const float2 ir23 = __half22float2(irh[hfi * 2 + 1]);
        const float2 iz01 = __half22float2(izh[hfi * 2]);
        const float2 iz23 = __half22float2(izh[hfi * 2 + 1]);
        const float2 in01 = __half22float2(inh[hfi * 2]);
        const float2 in23 = __half22float2(inh[hfi * 2 + 1]);

        float4 r;
        { const float rr = sigf(ir01.x + hr.x), zz = sigf(iz01.x + hz.x);
          r.x = (1.f - zz) * tanhfast(in01.x + rr * hn.x) + zz * hh.x; }
        { const float rr = sigf(ir01.y + hr.y), zz = sigf(iz01.y + hz.y);
          r.y = (1.f - zz) * tanhfast(in01.y + rr * hn.y) + zz * hh.y; }
        { const float rr = sigf(ir23.x + hr.z), zz = sigf(iz23.x + hz.z);
          r.z = (1.f - zz) * tanhfast(in23.x + rr * hn.z) + zz * hh.z; }
        { const float rr = sigf(ir23.y + hr.w), zz = sigf(iz23.y + hz.w);
          r.w = (1.f - zz) * tanhfast(in23.y + rr * hn.w) + zz * hh.w; }

        *reinterpret_cast<float4*>(hout + obase + hfi * 4) = r;
        reinterpret_cast<__half2*>(h16 + obase + hfi * 4)[0] = __floats2half2_rn(r.x, r.y);
        reinterpret_cast<__half2*>(h16 + obase + hfi * 4)[1] = __floats2half2_rn(r.z, r.w);
    }
}

// ---------------------------------------------------------------------------
__global__ void assemble_y_kernel(const float* __restrict__ o1, const float* __restrict__ o2,
                                  const int* __restrict__ cmap, float* __restrict__ y, int n4)
{
    const int idx = blockIdx.x * blockDim.x + threadIdx.x;
    if (idx >= n4) return;
    const int b   = idx >> 10;
    const int rem = idx & 1023;
    const int i   = rem >> 4;
    const int j0  = (rem & 15) * 4;
    const float v = __ldg(&o1[b * 64 + i]);
    float4 r = make_float4(v, v, v, v);
    const int k = cmap[(i >> 3) * 8 + (j0 >> 3)];
    if (k >= 0) {
        const int t = (i & 7) * 8 + (j0 & 7);
        const float4 a = *reinterpret_cast<const float4*>(o2 + ((long long)k * BSZ + b) * 64 + t);
        r.x += a.x; r.y += a.y; r.z += a.z; r.w += a.w;
    }
    *reinterpret_cast<float4*>(y + (long long)idx * 4) = r;
}

// ---------------------------------------------------------------------------
extern "C" void kernel_launch(void* const* d_in, const int* in_sizes, int n_in,
                              void* d_out, int out_size)
{
    const float* x    = (const float*)d_in[0];
    const float* h    = (const float*)d_in[1];
    const float* fa   = (const float*)d_in[2];
    const float* e1w  = (const float*)d_in[3];
    const float* e1b  = (const float*)d_in[4];
    const float* wih1 = (const float*)d_in[5];
    const float* whh1 = (const float*)d_in[6];
    const float* bih1 = (const float*)d_in[7];
    const float* bhh1 = (const float*)d_in[8];
    const float* o1w  = (const float*)d_in[9];
    const float* o1b  = (const float*)d_in[10];
    const float* e2w  = (const float*)d_in[11];
    const float* e2b  = (const float*)d_in[12];
    const float* wih2 = (const float*)d_in[13];
    const float* whh2 = (const float*)d_in[14];
    const float* bih2 = (const float*)d_in[15];
    const float* bhh2 = (const float*)d_in[16];
    const float* o2w  = (const float*)d_in[17];
    const float* o2b  = (const float*)d_in[18];
    float* out = (float*)d_out;

    const int B = in_sizes[0] / 4096;                  // 2048
    const long long YOFF = (long long)B * 4096;
    int Kc = (int)(((long long)out_size - YOFF) / ((long long)B * 256)) - 1;
    if (Kc < 0) Kc = 0;
    if (Kc > MAXK) Kc = MAXK;

    __half *p_xh, *p_hh, *p_e1h, *p_wi1h, *p_whhh, *p_o1wh, *p_o2wh,
           *p_x1h, *p_gi1h, *p_gi2h, *p_hh16, *p_w2ph;
    float *p_bhh, *p_xp, *p_gh12, *p_o, *p_b2p;
    int *p_cx, *p_cy, *p_cmap;
    cudaGetSymbolAddress((void**)&p_xh,   d_xh);
    cudaGetSymbolAddress((void**)&p_hh,   d_hh);
    cudaGetSymbolAddress((void**)&p_e1h,  d_e1h);
    cudaGetSymbolAddress((void**)&p_wi1h, d_wi1h);
    cudaGetSymbolAddress((void**)&p_whhh, d_whhh);
    cudaGetSymbolAddress((void**)&p_bhh,  d_bhh);
    cudaGetSymbolAddress((void**)&p_o1wh, d_o1wh);
    cudaGetSymbolAddress((void**)&p_o2wh, d_o2wh);
    cudaGetSymbolAddress((void**)&p_xp,   d_xp);
    cudaGetSymbolAddress((void**)&p_x1h,  d_x1h);
    cudaGetSymbolAddress((void**)&p_gh12, d_gh12);
    cudaGetSymbolAddress((void**)&p_gi1h, d_gi1h);
    cudaGetSymbolAddress((void**)&p_gi2h, d_gi2h);
    cudaGetSymbolAddress((void**)&p_hh16, d_hh16);
    cudaGetSymbolAddress((void**)&p_o,    d_o);
    cudaGetSymbolAddress((void**)&p_w2ph, d_w2ph);
    cudaGetSymbolAddress((void**)&p_b2p,  d_b2p);
    cudaGetSymbolAddress((void**)&p_cx,   d_cx);
    cudaGetSymbolAddress((void**)&p_cy,   d_cy);
    cudaGetSymbolAddress((void**)&p_cmap, d_cmap);

    const int SMB128 = 2 * CAS * (128 * ROWH + 128 * ROWH);  // 61440
    const int SMB64  = 2 * CAS * (128 * ROWH + 64 * ROWH);   // 46080
    cudaFuncSetAttribute((const void*)big_fused,  cudaFuncAttributeMaxDynamicSharedMemorySize, SMB128);
    cudaFuncSetAttribute((const void*)gi1_kernel, cudaFuncAttributeMaxDynamicSharedMemorySize, SMB64);
    cudaFuncSetAttribute((const void*)o_gemm,     cudaFuncAttributeMaxDynamicSharedMemorySize, SMB64);

    float* yh0 = out + YOFF;
    const int MB = B / 128;                       // 16
    const int nPrep = B * 4 + B / 4 + 1024 + 192 + 16 + 16 + 384 + 192 + 1;

    // 1) prep
    prep_kernel<<<nPrep, 256>>>(x, h, e1w, wih1, o1w, o2w, whh1, whh2, bhh1, bhh2,
                                wih2, e2w, e2b, bih2, fa,
                                p_xh, p_hh, p_e1h, p_wi1h, p_o1wh, p_o2wh,
                                p_whhh, p_bhh, p_w2ph, p_b2p,
                                p_cx, p_cy, p_cmap, B);

    // 2) x1-splitK ∥ gh12 ∥ gi2-multi (ZCH cells per block)
    const int nX1  = 2 * MB * 4;
    const int nGH  = 12 * MB;
    const int nZG  = (Kc + ZCH - 1) / ZCH;
    const int nGI2 = 6 * MB * nZG;
    big_fused<<<nX1 + nGH + nGI2, 256, SMB128>>>(
        p_xh, p_e1h, p_hh, p_whhh, p_bhh, p_w2ph, p_b2p,
        p_xp, p_gh12, p_gi2h, p_cx, p_cy, MB, nX1, nGH, Kc, B);

    // 3) reduce -> fp16 x1
    reduce_x1_kernel<<<(B * 64 + 255) / 256, 256>>>(p_xp, e1b, p_x1h, B * 64);

    // 4) gi1 (128x64 tiles, 192 blocks)
    gi1_kernel<<<dim3(12, MB), 256, SMB64>>>(p_x1h, p_wi1h, bih1, p_gi1h);

    // 5) all GRUs (8 elems/thread)
    gru_all_kernel<<<dim3((B * 32 + 255) / 256, 1, Kc + 1), 256>>>(
        p_gi1h, p_gi2h, p_gh12, h, yh0, p_hh16, B * 32, (long long)B);

    // 6) merged o GEMM
    o_gemm<<<dim3(1, MB, Kc + 1), 256, SMB64>>>(p_hh16, p_o1wh, p_o2wh, o1b, o2b, p_o, B);

    // 7) y = bcast(o1) + scatter(o2)
    assemble_y_kernel<<<(B * 1024 + 255) / 256, 256>>>(p_o, p_o + (long long)B * 64,
                                                       p_cmap, out, B * 1024);
}

// round 14
// speedup vs baseline: 1.5826x; 1.0099x over previous
#include <cuda_runtime.h>
#include <cuda_fp16.h>
#include <cstdint>

// ---------------------------------------------------------------------------
// FocDecoderRNN — R13 base + gi1(64x64, 30KB smem) merged with gru-cells
// (low-smem homogeneous merge; fixes R11's occupancy failure).
// Closed avenues: GRU-in-GEMM fusion, per-fragment cvt, cross-launch cell
// chunking, heavy-smem heterogeneous merge.
// ---------------------------------------------------------------------------

#define BSZ  2048
#define MAXK 64
#define ZCH  4        // cells per gi2 block

__device__ __half d_xh  [(size_t)BSZ * 4096];
__device__ __half d_hh  [BSZ * 256];
__device__ __half d_e1h [256 * 4096];
__device__ __half d_wi1h[768 * 256];
__device__ __half d_whhh[1536 * 256];
__device__ float  d_bhh [1536];
__device__ __half d_o1wh[64 * 256];
__device__ __half d_o2wh[64 * 256];
__device__ float  d_xp  [4 * BSZ * 256];
__device__ __half d_x1h [BSZ * 256];
__device__ float  d_gh12[(size_t)BSZ * 1536];
__device__ __half d_gi1h[BSZ * 768];
__device__ __half d_gi2h[(size_t)MAXK * BSZ * 768];
__device__ __half d_hh16[(size_t)(MAXK + 1) * BSZ * 256];
__device__ float  d_o   [(size_t)(MAXK + 1) * BSZ * 64];
__device__ __half d_w2ph[768 * 64];
__device__ float  d_b2p [768];
__device__ int    d_cx[MAXK], d_cy[MAXK], d_cmap[64];

// ---------------------------------------------------------------------------
__device__ __forceinline__ void mma_f16(float c[4], const uint32_t a[4], const uint32_t b[2])
{
    asm volatile(
        "mma.sync.aligned.m16n8k16.row.col.f32.f16.f16.f32 "
        "{%0,%1,%2,%3},{%4,%5,%6,%7},{%8,%9},{%0,%1,%2,%3};\n"
        : "+f"(c[0]), "+f"(c[1]), "+f"(c[2]), "+f"(c[3])
        : "r"(a[0]), "r"(a[1]), "r"(a[2]), "r"(a[3]), "r"(b[0]), "r"(b[1]));
}

__device__ __forceinline__ void cp16(uint32_t smem_addr, const void* gptr)
{
    asm volatile("cp.async.cg.shared.global [%0], [%1], 16;"
                 :: "r"(smem_addr), "l"(gptr));
}

__device__ __forceinline__ float sigf(float x)
{
    return __fdividef(1.f, 1.f + __expf(-x));
}
__device__ __forceinline__ float tanhfast(float x)
{
    return 1.f - __fdividef(2.f, __expf(2.f * x) + 1.f);
}

// ---------------------------------------------------------------------------
__device__ __forceinline__ void cvt_job(const float* __restrict__ s, __half* __restrict__ d,
                                        int grp)
{
    const float4 v = reinterpret_cast<const float4*>(s)[grp];
    reinterpret_cast<__half2*>(d)[grp * 2]     = __floats2half2_rn(v.x, v.y);
    reinterpret_cast<__half2*>(d)[grp * 2 + 1] = __floats2half2_rn(v.z, v.w);
}

__global__ void prep_kernel(const float* __restrict__ x,   const float* __restrict__ h,
                            const float* __restrict__ e1w, const float* __restrict__ wih1,
                            const float* __restrict__ o1w, const float* __restrict__ o2w,
                            const float* __restrict__ whh1, const float* __restrict__ whh2,
                            const float* __restrict__ bhh1, const float* __restrict__ bhh2,
                            const float* __restrict__ wih2, const float* __restrict__ e2w,
                            const float* __restrict__ e2b,  const float* __restrict__ bih2,
                            const float* __restrict__ fa,
                            __half* __restrict__ xh,  __half* __restrict__ hh,
                            __half* __restrict__ e1h, __half* __restrict__ wi1h,
                            __half* __restrict__ o1wh, __half* __restrict__ o2wh,
                            __half* __restrict__ whhh, float* __restrict__ bhh,
                            __half* __restrict__ w2ph, float* __restrict__ b2p,
                            int* __restrict__ cx, int* __restrict__ cy, int* __restrict__ cmap,
                            int B)
{
    const int bid = blockIdx.x;
    const int tid = threadIdx.x;
    const int b0 = B * 4;
    const int b1 = b0 + B / 4;
    const int b2 = b1 + 1024;
    const int b3 = b2 + 192;
    const int b4 = b3 + 16;
    const int b5 = b4 + 16;
    const int b6 = b5 + 384;
    const int b7 = b6 + 192;
    if (bid < b0)      { cvt_job(x,    xh,   bid * 256 + tid); }
    else if (bid < b1) { cvt_job(h,    hh,   (bid - b0) * 256 + tid); }
    else if (bid < b2) { cvt_job(e1w,  e1h,  (bid - b1) * 256 + tid); }
    else if (bid < b3) { cvt_job(wih1, wi1h, (bid - b2) * 256 + tid); }
    else if (bid < b4) { cvt_job(o1w,  o1wh, (bid - b3) * 256 + tid); }
    else if (bid < b5) { cvt_job(o2w,  o2wh, (bid - b4) * 256 + tid); }
    else if (bid < b6) {
        const int i = (bid - b5) * 256 + tid;
        const int e = i * 4, row = e >> 8, col = e & 255;
        const float* src = (row < 768) ? (whh1 + row * 256 + col)
                                       : (whh2 + (row - 768) * 256 + col);
        const float4 v = *reinterpret_cast<const float4*>(src);
        reinterpret_cast<__half2*>(whhh)[i * 2]     = __floats2half2_rn(v.x, v.y);
        reinterpret_cast<__half2*>(whhh)[i * 2 + 1] = __floats2half2_rn(v.z, v.w);
        if (i < 1536) bhh[i] = (i < 768) ? bhh1[i] : bhh2[i - 768];
    } else if (bid < b7) {
        const int n = (bid - b6) * 4 + (tid >> 6);
        const int t = tid & 63;
        float s = 0.f;
        for (int c = 0; c < 256; c++)
            s += wih2[n * 256 + c] * e2w[c * 64 + t];
        w2ph[n * 64 + t] = __float2half_rn(s);
        if (t == 0) {
            float sb = 0.f;
            for (int c = 0; c < 256; c++) sb += wih2[n * 256 + c] * e2b[c];
            b2p[n] = bih2[n] + sb;
        }
    } else {
        if (tid == 0) {
            for (int i = 0; i < 64; i++) cmap[i] = -1;
            int k = 0;
            for (int i = 0; i < 8; i++)
                for (int j = 0; j < 8; j++)
                    if (fa[i * 8 + j] > 0.5f) { cx[k] = i; cy[k] = j; cmap[i * 8 + j] = k; k++; }
        }
    }
}

// ---------------------------------------------------------------------------
// FP16 GEMM-NT device core (cp.async 3-stage, K-slab 32, m16n8k16).
#define CAS  3
#define ROWH 40

template<int AMODE, int NT, int HOUT, int MT>
__device__ __forceinline__
void gemm_dev(const __half* __restrict__ A, const __half* __restrict__ Bw,
              const float* __restrict__ bias, void* __restrict__ Cv,
              int N, int K, int lda, int ldb,
              long long sAz, long long sBz, long long sCz,
              const int* __restrict__ cxs, const int* __restrict__ cys,
              int bx, int by, int bz)
{
    constexpr int STG_A = MT * ROWH;
    constexpr int STG_B = NT * ROWH;
    constexpr int WNW   = (NT == 128) ? 4 : 2;
    constexpr int MF    = MT * WNW / 128;

    extern __shared__ __half smh[];
    const uint32_t smBase = (uint32_t)__cvta_generic_to_shared(smh);

    const int bm = by * MT;
    const int bn = bx * NT;
    int cellBase = 0;
    if (AMODE == 1) cellBase = cxs[bz] * 512 + cys[bz] * 8;
    if (AMODE == 0) A += (long long)bz * sAz;
    Bw += (long long)bz * sBz;

    const int tid  = threadIdx.x;
    const int lane = tid & 31;
    const int wid  = tid >> 5;
    const int wm   = wid / WNW;
    const int wn   = wid % WNW;
    const int g    = lane >> 2;
    const int t2   = (lane & 3) * 2;
    const int alr  = (MT == 128) ? (tid >> 1) : (tid >> 2);
    const int alk  = (MT == 128) ? (tid & 1) * 16 : (tid & 3) * 8;
    const int br   = (NT == 128) ? (tid >> 1) : (tid >> 2);
    const int bc   = (NT == 128) ? (tid & 1) * 16 : (tid & 3) * 8;

    float acc[MF][4][4];
#pragma unroll
    for (int i = 0; i < MF; i++)
#pragma unroll
        for (int j = 0; j < 4; j++)
#pragma unroll
            for (int q = 0; q < 4; q++) acc[i][j][q] = 0.f;

    auto issue = [&](int stg, int k0) {
        const __half *ap0, *ap1;
        if (AMODE == 0) {
            ap0 = A + (long long)(bm + alr) * lda + k0 + alk;
            ap1 = ap0 + 8;
        } else {
            const int tt = k0 + alk;
            const __half* base = A + (long long)(bm + alr) * 4096 + cellBase;
            ap0 = base + ((tt >> 3) << 6);
            ap1 = base + (((tt + 8) >> 3) << 6);
        }
        const uint32_t da = smBase + 2u * (stg * STG_A + alr * ROWH + alk);
        cp16(da, ap0);
        if (MT == 128) cp16(da + 16, ap1);
        const __half* bp = Bw + (long long)(bn + br) * ldb + k0 + bc;
        const uint32_t db = smBase + 2u * (CAS * STG_A + stg * STG_B + br * ROWH + bc);
        cp16(db, bp);
        if (NT == 128) cp16(db + 16, bp + 8);
    };

    const int nIter = K >> 5;
#pragma unroll
    for (int s = 0; s < CAS - 1; s++) {
        if (s < nIter) issue(s, s * 32);
        asm volatile("cp.async.commit_group;");
    }

    for (int it = 0; it < nIter; it++) {
        const int cur = it % CAS;
        asm volatile("cp.async.wait_group %0;" :: "n"(CAS - 2));
        __syncthreads();

        const __half* Ab = smh + cur * STG_A;
        const __half* Bb = smh + CAS * STG_A + cur * STG_B;
#pragma unroll
        for (int kk = 0; kk < 32; kk += 16) {
            uint32_t af[MF][4], bf[4][2];
#pragma unroll
            for (int i = 0; i < MF; i++) {
                const int m = wm * (MF * 16) + i * 16;
                af[i][0] = *reinterpret_cast<const uint32_t*>(Ab + (m + g) * ROWH + kk + t2);
                af[i][1] = *reinterpret_cast<const uint32_t*>(Ab + (m + 8 + g) * ROWH + kk + t2);
                af[i][2] = *reinterpret_cast<const uint32_t*>(Ab + (m + g) * ROWH + kk + t2 + 8);
                af[i][3] = *reinterpret_cast<const uint32_t*>(Ab + (m + 8 + g) * ROWH + kk + t2 + 8);
            }
#pragma unroll
            for (int j = 0; j < 4; j++) {
                const int n = wn * 32 + j * 8;
                bf[j][0] = *reinterpret_cast<const uint32_t*>(Bb + (n + g) * ROWH + kk + t2);
                bf[j][1] = *reinterpret_cast<const uint32_t*>(Bb + (n + g) * ROWH + kk + t2 + 8);
            }
#pragma unroll
            for (int i = 0; i < MF; i++)
#pragma unroll
                for (int j = 0; j < 4; j++) mma_f16(acc[i][j], af[i], bf[j]);
        }
        const int nk = it + CAS - 1;
        if (nk < nIter) issue(nk % CAS, nk * 32);
        asm volatile("cp.async.commit_group;");
    }

    float* Cf = (float*)Cv;
    __half* Ch = (__half*)Cv;
#pragma unroll
    for (int i = 0; i < MF; i++) {
        const int row0 = bm + wm * (MF * 16) + i * 16 + g;
#pragma unroll
        for (int j = 0; j < 4; j++) {
            const int col = bn + wn * 32 + j * 8 + t2;
            float bz0 = 0.f, bz1 = 0.f;
            if (bias) { bz0 = __ldg(&bias[col]); bz1 = __ldg(&bias[col + 1]); }
            const float v0 = acc[i][j][0] + bz0, v1 = acc[i][j][1] + bz1;
            const float v2 = acc[i][j][2] + bz0, v3 = acc[i][j][3] + bz1;
            if (HOUT == 0) {
                float* C = Cf + (long long)bz * sCz;
                *reinterpret_cast<float2*>(&C[(long long)row0 * N + col]) = make_float2(v0, v1);
                *reinterpret_cast<float2*>(&C[(long long)(row0 + 8) * N + col]) = make_float2(v2, v3);
            } else {
                __half* C = Ch + (long long)bz * sCz;
                *reinterpret_cast<__half2*>(&C[(long long)row0 * N + col]) =
                    __floats2half2_rn(v0, v1);
                *reinterpret_cast<__half2*>(&C[(long long)(row0 + 8) * N + col]) =
                    __floats2half2_rn(v2, v3);
            }
        }
    }
}

// ---------------------------------------------------------------------------
// gi2 multi-cell: one 128x128 tile position, ZCH cells per block.
#define ROW2 72

__device__ __forceinline__
void gi2_multi(const __half* __restrict__ xh, const __half* __restrict__ w2ph,
               const float* __restrict__ b2p, __half* __restrict__ gi2h,
               const int* __restrict__ cxs, const int* __restrict__ cys,
               int bx, int by, int z0, int zn, int B)
{
    extern __shared__ __half smh[];
    const uint32_t smBase = (uint32_t)__cvta_generic_to_shared(smh);
    const uint32_t bOff = 2 * 128 * ROW2;

    const int bm = by * 128;
    const int bn = bx * 128;

    const int tid  = threadIdx.x;
    const int lane = tid & 31;
    const int wid  = tid >> 5;
    const int wm   = wid >> 2;
    const int wn   = wid & 3;
    const int g    = lane >> 2;
    const int t2   = (lane & 3) * 2;
    const int lr   = tid >> 1;
    const int lc   = (tid & 1) * 32;

    auto issueA = [&](int buf, int zi) {
        const int cellBase = cxs[z0 + zi] * 512 + cys[z0 + zi] * 8;
        const __half* base = xh + (long long)(bm + lr) * 4096 + cellBase + (lc >> 3) * 64;
        const uint32_t da = smBase + 2u * ((buf * 128 + lr) * ROW2 + lc);
#pragma unroll
        for (int q = 0; q < 4; q++)
            cp16(da + q * 16, base + q * 64);
    };

    {
        const __half* bp = w2ph + (long long)(bn + lr) * 64 + lc;
        const uint32_t db = smBase + 2u * (bOff + lr * ROW2 + lc);
#pragma unroll
        for (int q = 0; q < 4; q++)
            cp16(db + q * 16, bp + q * 8);
    }
    issueA(0, 0);
    asm volatile("cp.async.commit_group;");

    float bzv[4][2];
#pragma unroll
    for (int j = 0; j < 4; j++) {
        const int col = bn + wn * 32 + j * 8 + t2;
        bzv[j][0] = __ldg(&b2p[col]);
        bzv[j][1] = __ldg(&b2p[col + 1]);
    }

    const __half* Bs = smh + bOff;
    for (int zi = 0; zi < zn; zi++) {
        if (zi + 1 < zn) issueA((zi + 1) & 1, zi + 1);
        asm volatile("cp.async.commit_group;");
        asm volatile("cp.async.wait_group 1;");
        __syncthreads();

        const __half* Ab = smh + ((zi & 1) * 128) * ROW2;
        float acc[4][4][4];
#pragma unroll
        for (int i = 0; i < 4; i++)
#pragma unroll
            for (int j = 0; j < 4; j++)
#pragma unroll
                for (int q = 0; q < 4; q++) acc[i][j][q] = 0.f;

#pragma unroll
        for (int kk = 0; kk < 64; kk += 16) {
            uint32_t af[4][4], bf[4][2];
#pragma unroll
            for (int i = 0; i < 4; i++) {
                const int m = wm * 64 + i * 16;
                af[i][0] = *reinterpret_cast<const uint32_t*>(Ab + (m + g) * ROW2 + kk + t2);
                af[i][1] = *reinterpret_cast<const uint32_t*>(Ab + (m + 8 + g) * ROW2 + kk + t2);
                af[i][2] = *reinterpret_cast<const uint32_t*>(Ab + (m + g) * ROW2 + kk + t2 + 8);
                af[i][3] = *reinterpret_cast<const uint32_t*>(Ab + (m + 8 + g) * ROW2 + kk + t2 + 8);
            }
#pragma unroll
            for (int j = 0; j < 4; j++) {
                const int n = wn * 32 + j * 8;
                bf[j][0] = *reinterpret_cast<const uint32_t*>(Bs + (n + g) * ROW2 + kk + t2);
                bf[j][1] = *reinterpret_cast<const uint32_t*>(Bs + (n + g) * ROW2 + kk + t2 + 8);
            }
#pragma unroll
            for (int i = 0; i < 4; i++)
#pragma unroll
                for (int j = 0; j < 4; j++) mma_f16(acc[i][j], af[i], bf[j]);
        }

        __half* C = gi2h + (long long)(z0 + zi) * B * 768;
#pragma unroll
        for (int i = 0; i < 4; i++) {
            const int row0 = bm + wm * 64 + i * 16 + g;
#pragma unroll
            for (int j = 0; j < 4; j++) {
                const int col = bn + wn * 32 + j * 8 + t2;
                *reinterpret_cast<__half2*>(&C[(long long)row0 * 768 + col]) =
                    __floats2half2_rn(acc[i][j][0] + bzv[j][0], acc[i][j][1] + bzv[j][1]);
                *reinterpret_cast<__half2*>(&C[(long long)(row0 + 8) * 768 + col]) =
                    __floats2half2_rn(acc[i][j][2] + bzv[j][0], acc[i][j][3] + bzv[j][1]);
            }
        }
        __syncthreads();
    }
}

// ---------------------------------------------------------------------------
// big_fused: x1-splitK | gh12 | gi2-multi(all cells)
__global__ __launch_bounds__(256)
void big_fused(const __half* __restrict__ xh, const __half* __restrict__ e1h,
               const __half* __restrict__ hh, const __half* __restrict__ whhh,
               const float* __restrict__ bhh, const __half* __restrict__ w2ph,
               const float* __restrict__ b2p,
               float* __restrict__ xp, float* __restrict__ gh12,
               __half* __restrict__ gi2h,
               const int* __restrict__ cxs, const int* __restrict__ cys,
               int MB, int nX1, int nGH, int Kc, int B)
{
    const int i = blockIdx.x;
    if (i < nX1) {
        const int bx = i & 1, r = i >> 1;
        gemm_dev<0, 128, 0, 128>(xh, e1h, nullptr, xp, 256, 1024, 4096, 4096,
                                 1024, 1024, (long long)B * 256, nullptr, nullptr,
                                 bx, r % MB, r / MB);
    } else if (i < nX1 + nGH) {
        const int j = i - nX1;
        gemm_dev<0, 128, 0, 128>(hh, whhh, bhh, gh12, 1536, 256, 256, 256,
                                 0, 0, 0, nullptr, nullptr,
                                 j % 12, j / 12, 0);
    } else {
        const int k = i - nX1 - nGH;
        const int bx = k % 6, r = k / 6;
        const int by = r % MB, zg = r / MB;
        const int z0 = zg * ZCH;
        const int zn = (Kc - z0 < ZCH) ? (Kc - z0) : ZCH;
        gi2_multi(xh, w2ph, b2p, gi2h, cxs, cys, bx, by, z0, zn, B);
    }
}

// ---------------------------------------------------------------------------
// GRU 8-elems/thread core
__device__ __forceinline__
void gru8_core(const __half* __restrict__ g, const float* __restrict__ q,
               const float* __restrict__ h0, float* __restrict__ hout,
               __half* __restrict__ h16, long long zslot, int idx, long long Bll)
{
    const int b = idx >> 5;
    const int j = (idx & 31) * 8;
    const __half* gp = g + (long long)b * 768;
    const float* qp  = q + (long long)b * 1536;

    const uint4 irU = *reinterpret_cast<const uint4*>(gp + j);
    const uint4 izU = *reinterpret_cast<const uint4*>(gp + 256 + j);
    const uint4 inU = *reinterpret_cast<const uint4*>(gp + 512 + j);
    const __half2* irh = reinterpret_cast<const __half2*>(&irU);
    const __half2* izh = reinterpret_cast<const __half2*>(&izU);
    const __half2* inh = reinterpret_cast<const __half2*>(&inU);

    const long long obase = zslot * (Bll * 256) + (long long)b * 256 + j;

#pragma unroll
    for (int hfi = 0; hfi < 2; hfi++) {
        const int jj = j + hfi * 4;
        const float4 hr = *reinterpret_cast<const float4*>(qp + jj);
        const float4 hz = *reinterpret_cast<const float4*>(qp + 256 + jj);
        const float4 hn = *reinterpret_cast<const float4*>(qp + 512 + jj);
        const float4 hh = *reinterpret_cast<const float4*>(h0 + (long long)b * 256 + jj);
        const float2 ir01 = __half22float2(irh[hfi * 2]);
        const float2 ir23 = __half22float2(irh[hfi * 2 + 1]);
        const float2 iz01 = __half22float2(izh[hfi * 2]);
        const float2 iz23 = __half22float2(izh[hfi * 2 + 1]);
        const float2 in01 = __half22float2(inh[hfi * 2]);
        const float2 in23 = __half22float2(inh[hfi * 2 + 1]);

        float4 r;
        { const float rr = sigf(ir01.x + hr.x), zz = sigf(iz01.x + hz.x);
          r.x = (1.f - zz) * tanhfast(in01.x + rr * hn.x) + zz * hh.x; }
        { const float rr = sigf(ir01.y + hr.y), zz = sigf(iz01.y + hz.y);
          r.y = (1.f - zz) * tanhfast(in01.y + rr * hn.y) + zz * hh.y; }
        { const float rr = sigf(ir23.x + hr.z), zz = sigf(iz23.x + hz.z);
          r.z = (1.f - zz) * tanhfast(in23.x + rr * hn.z) + zz * hh.z; }
        { const float rr = sigf(ir23.y + hr.w), zz = sigf(iz23.y + hz.w);
          r.w = (1.f - zz) * tanhfast(in23.y + rr * hn.w) + zz * hh.w; }

        *reinterpret_cast<float4*>(hout + obase + hfi * 4) = r;
        reinterpret_cast<__half2*>(h16 + obase + hfi * 4)[0] = __floats2half2_rn(r.x, r.y);
        reinterpret_cast<__half2*>(h16 + obase + hfi * 4)[1] = __floats2half2_rn(r.z, r.w);
    }
}

// ---------------------------------------------------------------------------
// gi1 (64x64 tiles, 30KB smem) ∥ gru-cells — low-smem homogeneous merge.
__global__ __launch_bounds__(256)
void gi1_gru_cells(const __half* __restrict__ x1h, const __half* __restrict__ wi1h,
                   const float* __restrict__ bih1, __half* __restrict__ gi1h,
                   const __half* __restrict__ gi2h, const float* __restrict__ gh12,
                   const float* __restrict__ h0,
                   float* __restrict__ hout, __half* __restrict__ h16,
                   int nGi1, int B)
{
    const int i = blockIdx.x;
    if (i < nGi1) {
        gemm_dev<0, 64, 1, 64>(x1h, wi1h, bih1, gi1h, 768, 256, 256, 256,
                               0, 0, 0, nullptr, nullptr,
                               i % 12, i / 12, 0);
    } else {
        const int j = i - nGi1;
        const int z = j >> 8;                       // 256 blocks per cell
        const int idx = (j & 255) * 256 + threadIdx.x;   // over B*32
        if (idx < B * 32)
            gru8_core(gi2h + (long long)z * B * 768, gh12 + 768, h0,
                      hout, h16, z + 1, idx, (long long)B);
    }
}

// gru layer-1
__global__ void gru_l1_kernel(const __half* __restrict__ gi1h, const float* __restrict__ gh12,
                              const float* __restrict__ h0,
                              float* __restrict__ hout, __half* __restrict__ h16, int B)
{
    const int idx = blockIdx.x * blockDim.x + threadIdx.x;
    if (idx < B * 32)
        gru8_core(gi1h, gh12, h0, hout, h16, 0, idx, (long long)B);
}

// merged o GEMM
__global__ __launch_bounds__(256)
void o_gemm(const __half* __restrict__ A,
            const __half* __restrict__ Bw, const __half* __restrict__ Bw2,
            const float* __restrict__ bias, const float* __restrict__ bias2,
            float* __restrict__ C, int B)
{
    const __half* B_ = (blockIdx.z > 0) ? Bw2 : Bw;
    const float* bi  = (blockIdx.z > 0) ? bias2 : bias;
    gemm_dev<0, 64, 0, 128>(A, B_, bi, C, 64, 256, 256, 256,
                            (long long)B * 256, 0, (long long)B * 64,
                            nullptr, nullptr, blockIdx.x, blockIdx.y, blockIdx.z);
}

// ---------------------------------------------------------------------------
__global__ void reduce_x1_kernel(const float* __restrict__ P, const float* __restrict__ bias,
                                 __half* __restrict__ x1, int n4)
{
    const int idx = blockIdx.x * blockDim.x + threadIdx.x;
    if (idx >= n4) return;
    const float4 p0 = *reinterpret_cast<const float4*>(P + (size_t)0 * BSZ * 256 + idx * 4);
    const float4 p1 = *reinterpret_cast<const float4*>(P + (size_t)1 * BSZ * 256 + idx * 4);
    const float4 p2 = *reinterpret_cast<const float4*>(P + (size_t)2 * BSZ * 256 + idx * 4);
    const float4 p3 = *reinterpret_cast<const float4*>(P + (size_t)3 * BSZ * 256 + idx * 4);
    const int j0 = (idx * 4) & 255;
    const float4 b = *reinterpret_cast<const float4*>(bias + j0);
    reinterpret_cast<__half2*>(x1)[idx * 2] =
        __floats2half2_rn(p0.x + p1.x + p2.x + p3.x + b.x,
                          p0.y + p1.y + p2.y + p3.y + b.y);
    reinterpret_cast<__half2*>(x1)[idx * 2 + 1] =
        __floats2half2_rn(p0.z + p1.z + p2.z + p3.z + b.z,
                          p0.w + p1.w + p2.w + p3.w + b.w);
}

// ---------------------------------------------------------------------------
__global__ void assemble_y_kernel(const float* __restrict__ o1, const float* __restrict__ o2,
                                  const int* __restrict__ cmap, float* __restrict__ y, int n4)
{
    const int idx = blockIdx.x * blockDim.x + threadIdx.x;
    if (idx >= n4) return;
    const int b   = idx >> 10;
    const int rem = idx & 1023;
    const int i   = rem >> 4;
    const int j0  = (rem & 15) * 4;
    const float v = __ldg(&o1[b * 64 + i]);
    float4 r = make_float4(v, v, v, v);
    const int k = cmap[(i >> 3) * 8 + (j0 >> 3)];
    if (k >= 0) {
        const int t = (i & 7) * 8 + (j0 & 7);
        const float4 a = *reinterpret_cast<const float4*>(o2 + ((long long)k * BSZ + b) * 64 + t);
        r.x += a.x; r.y += a.y; r.z += a.z; r.w += a.w;
    }
    *reinterpret_cast<float4*>(y + (long long)idx * 4) = r;
}

// ---------------------------------------------------------------------------
extern "C" void kernel_launch(void* const* d_in, const int* in_sizes, int n_in,
                              void* d_out, int out_size)
{
    const float* x    = (const float*)d_in[0];
    const float* h    = (const float*)d_in[1];
    const float* fa   = (const float*)d_in[2];
    const float* e1w  = (const float*)d_in[3];
    const float* e1b  = (const float*)d_in[4];
    const float* wih1 = (const float*)d_in[5];
    const float* whh1 = (const float*)d_in[6];
    const float* bih1 = (const float*)d_in[7];
    const float* bhh1 = (const float*)d_in[8];
    const float* o1w  = (const float*)d_in[9];
    const float* o1b  = (const float*)d_in[10];
    const float* e2w  = (const float*)d_in[11];
    const float* e2b  = (const float*)d_in[12];
    const float* wih2 = (const float*)d_in[13];
    const float* whh2 = (const float*)d_in[14];
    const float* bih2 = (const float*)d_in[15];
    const float* bhh2 = (const float*)d_in[16];
    const float* o2w  = (const float*)d_in[17];
    const float* o2b  = (const float*)d_in[18];
    float* out = (float*)d_out;

    const int B = in_sizes[0] / 4096;                  // 2048
    const long long YOFF = (long long)B * 4096;
    int Kc = (int)(((long long)out_size - YOFF) / ((long long)B * 256)) - 1;
    if (Kc < 0) Kc = 0;
    if (Kc > MAXK) Kc = MAXK;

    __half *p_xh, *p_hh, *p_e1h, *p_wi1h, *p_whhh, *p_o1wh, *p_o2wh,
           *p_x1h, *p_gi1h, *p_gi2h, *p_hh16, *p_w2ph;
    float *p_bhh, *p_xp, *p_gh12, *p_o, *p_b2p;
    int *p_cx, *p_cy, *p_cmap;
    cudaGetSymbolAddress((void**)&p_xh,   d_xh);
    cudaGetSymbolAddress((void**)&p_hh,   d_hh);
    cudaGetSymbolAddress((void**)&p_e1h,  d_e1h);
    cudaGetSymbolAddress((void**)&p_wi1h, d_wi1h);
    cudaGetSymbolAddress((void**)&p_whhh, d_whhh);
    cudaGetSymbolAddress((void**)&p_bhh,  d_bhh);
    cudaGetSymbolAddress((void**)&p_o1wh, d_o1wh);
    cudaGetSymbolAddress((void**)&p_o2wh, d_o2wh);
    cudaGetSymbolAddress((void**)&p_xp,   d_xp);
    cudaGetSymbolAddress((void**)&p_x1h,  d_x1h);
    cudaGetSymbolAddress((void**)&p_gh12, d_gh12);
    cudaGetSymbolAddress((void**)&p_gi1h, d_gi1h);
    cudaGetSymbolAddress((void**)&p_gi2h, d_gi2h);
    cudaGetSymbolAddress((void**)&p_hh16, d_hh16);
    cudaGetSymbolAddress((void**)&p_o,    d_o);
    cudaGetSymbolAddress((void**)&p_w2ph, d_w2ph);
    cudaGetSymbolAddress((void**)&p_b2p,  d_b2p);
    cudaGetSymbolAddress((void**)&p_cx,   d_cx);
    cudaGetSymbolAddress((void**)&p_cy,   d_cy);
    cudaGetSymbolAddress((void**)&p_cmap, d_cmap);

    const int SMB128 = 2 * CAS * (128 * ROWH + 128 * ROWH);  // 61440
    const int SMB64  = 2 * CAS * (128 * ROWH + 64 * ROWH);   // 46080
    const int SMB44  = 2 * CAS * (64 * ROWH + 64 * ROWH);    // 30720 (gi1 64x64)
    cudaFuncSetAttribute((const void*)big_fused,     cudaFuncAttributeMaxDynamicSharedMemorySize, SMB128);
    cudaFuncSetAttribute((const void*)gi1_gru_cells, cudaFuncAttributeMaxDynamicSharedMemorySize, SMB44);
    cudaFuncSetAttribute((const void*)o_gemm,        cudaFuncAttributeMaxDynamicSharedMemorySize, SMB64);

    float* yh0 = out + YOFF;
    const int MB = B / 128;                       // 16
    const int nPrep = B * 4 + B / 4 + 1024 + 192 + 16 + 16 + 384 + 192 + 1;

    // 1) prep
    prep_kernel<<<nPrep, 256>>>(x, h, e1w, wih1, o1w, o2w, whh1, whh2, bhh1, bhh2,
                                wih2, e2w, e2b, bih2, fa,
                                p_xh, p_hh, p_e1h, p_wi1h, p_o1wh, p_o2wh,
                                p_whhh, p_bhh, p_w2ph, p_b2p,
                                p_cx, p_cy, p_cmap, B);

    // 2) x1-splitK ∥ gh12 ∥ gi2-multi
    const int nX1  = 2 * MB * 4;
    const int nGH  = 12 * MB;
    const int nZG  = (Kc + ZCH - 1) / ZCH;
    const int nGI2 = 6 * MB * nZG;
    big_fused<<<nX1 + nGH + nGI2, 256, SMB128>>>(
        p_xh, p_e1h, p_hh, p_whhh, p_bhh, p_w2ph, p_b2p,
        p_xp, p_gh12, p_gi2h, p_cx, p_cy, MB, nX1, nGH, Kc, B);

    // 3) reduce -> fp16 x1
    reduce_x1_kernel<<<(B * 64 + 255) / 256, 256>>>(p_xp, e1b, p_x1h, B * 64);

    // 4) gi1 (64x64, 30KB smem) ∥ gru-cells
    const int nGi1 = 12 * (B / 64);                 // 384
    const int nGruC = ((B * 32 + 255) / 256) * Kc;  // 256 * Kc
    gi1_gru_cells<<<nGi1 + nGruC, 256, SMB44>>>(
        p_x1h, p_wi1h, bih1, p_gi1h, p_gi2h, p_gh12, h, yh0, p_hh16, nGi1, B);

    // 5) gru layer-1
    gru_l1_kernel<<<(B * 32 + 255) / 256, 256>>>(p_gi1h, p_gh12, h, yh0, p_hh16, B);

    // 6) merged o GEMM
    o_gemm<<<dim3(1, MB, Kc + 1), 256, SMB64>>>(p_hh16, p_o1wh, p_o2wh, o1b, o2b, p_o, B);

    // 7) y = bcast(o1) + scatter(o2)
    assemble_y_kernel<<<(B * 1024 + 255) / 256, 256>>>(p_o, p_o + (long long)B * 64,
                                                       p_cmap, out, B * 1024);
}

// round 15
// speedup vs baseline: 1.6646x; 1.0518x over previous
#include <cuda_runtime.h>
#include <cuda_fp16.h>
#include <cstdint>

// ---------------------------------------------------------------------------
// FocDecoderRNN — R14 base + fp16 gh12 buffer (halves the GRU stream's L2
// traffic and load-instruction count).
// Closed avenues: GRU-in-GEMM fusion, per-fragment cvt, cross-launch cell
// chunking, heavy-smem heterogeneous merge.
// ---------------------------------------------------------------------------

#define BSZ  2048
#define MAXK 64
#define ZCH  4        // cells per gi2 block

__device__ __half d_xh  [(size_t)BSZ * 4096];
__device__ __half d_hh  [BSZ * 256];
__device__ __half d_e1h [256 * 4096];
__device__ __half d_wi1h[768 * 256];
__device__ __half d_whhh[1536 * 256];
__device__ float  d_bhh [1536];
__device__ __half d_o1wh[64 * 256];
__device__ __half d_o2wh[64 * 256];
__device__ float  d_xp  [4 * BSZ * 256];
__device__ __half d_x1h [BSZ * 256];
__device__ __half d_gh12h[(size_t)BSZ * 1536];     // fp16 h-gate buffer
__device__ __half d_gi1h[BSZ * 768];
__device__ __half d_gi2h[(size_t)MAXK * BSZ * 768];
__device__ __half d_hh16[(size_t)(MAXK + 1) * BSZ * 256];
__device__ float  d_o   [(size_t)(MAXK + 1) * BSZ * 64];
__device__ __half d_w2ph[768 * 64];
__device__ float  d_b2p [768];
__device__ int    d_cx[MAXK], d_cy[MAXK], d_cmap[64];

// ---------------------------------------------------------------------------
__device__ __forceinline__ void mma_f16(float c[4], const uint32_t a[4], const uint32_t b[2])
{
    asm volatile(
        "mma.sync.aligned.m16n8k16.row.col.f32.f16.f16.f32 "
        "{%0,%1,%2,%3},{%4,%5,%6,%7},{%8,%9},{%0,%1,%2,%3};\n"
        : "+f"(c[0]), "+f"(c[1]), "+f"(c[2]), "+f"(c[3])
        : "r"(a[0]), "r"(a[1]), "r"(a[2]), "r"(a[3]), "r"(b[0]), "r"(b[1]));
}

__device__ __forceinline__ void cp16(uint32_t smem_addr, const void* gptr)
{
    asm volatile("cp.async.cg.shared.global [%0], [%1], 16;"
                 :: "r"(smem_addr), "l"(gptr));
}

__device__ __forceinline__ float sigf(float x)
{
    return __fdividef(1.f, 1.f + __expf(-x));
}
__device__ __forceinline__ float tanhfast(float x)
{
    return 1.f - __fdividef(2.f, __expf(2.f * x) + 1.f);
}

// ---------------------------------------------------------------------------
__device__ __forceinline__ void cvt_job(const float* __restrict__ s, __half* __restrict__ d,
                                        int grp)
{
    const float4 v = reinterpret_cast<const float4*>(s)[grp];
    reinterpret_cast<__half2*>(d)[grp * 2]     = __floats2half2_rn(v.x, v.y);
    reinterpret_cast<__half2*>(d)[grp * 2 + 1] = __floats2half2_rn(v.z, v.w);
}

__global__ void prep_kernel(const float* __restrict__ x,   const float* __restrict__ h,
                            const float* __restrict__ e1w, const float* __restrict__ wih1,
                            const float* __restrict__ o1w, const float* __restrict__ o2w,
                            const float* __restrict__ whh1, const float* __restrict__ whh2,
                            const float* __restrict__ bhh1, const float* __restrict__ bhh2,
                            const float* __restrict__ wih2, const float* __restrict__ e2w,
                            const float* __restrict__ e2b,  const float* __restrict__ bih2,
                            const float* __restrict__ fa,
                            __half* __restrict__ xh,  __half* __restrict__ hh,
                            __half* __restrict__ e1h, __half* __restrict__ wi1h,
                            __half* __restrict__ o1wh, __half* __restrict__ o2wh,
                            __half* __restrict__ whhh, float* __restrict__ bhh,
                            __half* __restrict__ w2ph, float* __restrict__ b2p,
                            int* __restrict__ cx, int* __restrict__ cy, int* __restrict__ cmap,
                            int B)
{
    const int bid = blockIdx.x;
    const int tid = threadIdx.x;
    const int b0 = B * 4;
    const int b1 = b0 + B / 4;
    const int b2 = b1 + 1024;
    const int b3 = b2 + 192;
    const int b4 = b3 + 16;
    const int b5 = b4 + 16;
    const int b6 = b5 + 384;
    const int b7 = b6 + 192;
    if (bid < b0)      { cvt_job(x,    xh,   bid * 256 + tid); }
    else if (bid < b1) { cvt_job(h,    hh,   (bid - b0) * 256 + tid); }
    else if (bid < b2) { cvt_job(e1w,  e1h,  (bid - b1) * 256 + tid); }
    else if (bid < b3) { cvt_job(wih1, wi1h, (bid - b2) * 256 + tid); }
    else if (bid < b4) { cvt_job(o1w,  o1wh, (bid - b3) * 256 + tid); }
    else if (bid < b5) { cvt_job(o2w,  o2wh, (bid - b4) * 256 + tid); }
    else if (bid < b6) {
        const int i = (bid - b5) * 256 + tid;
        const int e = i * 4, row = e >> 8, col = e & 255;
        const float* src = (row < 768) ? (whh1 + row * 256 + col)
                                       : (whh2 + (row - 768) * 256 + col);
        const float4 v = *reinterpret_cast<const float4*>(src);
        reinterpret_cast<__half2*>(whhh)[i * 2]     = __floats2half2_rn(v.x, v.y);
        reinterpret_cast<__half2*>(whhh)[i * 2 + 1] = __floats2half2_rn(v.z, v.w);
        if (i < 1536) bhh[i] = (i < 768) ? bhh1[i] : bhh2[i - 768];
    } else if (bid < b7) {
        const int n = (bid - b6) * 4 + (tid >> 6);
        const int t = tid & 63;
        float s = 0.f;
        for (int c = 0; c < 256; c++)
            s += wih2[n * 256 + c] * e2w[c * 64 + t];
        w2ph[n * 64 + t] = __float2half_rn(s);
        if (t == 0) {
            float sb = 0.f;
            for (int c = 0; c < 256; c++) sb += wih2[n * 256 + c] * e2b[c];
            b2p[n] = bih2[n] + sb;
        }
    } else {
        if (tid == 0) {
            for (int i = 0; i < 64; i++) cmap[i] = -1;
            int k = 0;
            for (int i = 0; i < 8; i++)
                for (int j = 0; j < 8; j++)
                    if (fa[i * 8 + j] > 0.5f) { cx[k] = i; cy[k] = j; cmap[i * 8 + j] = k; k++; }
        }
    }
}

// ---------------------------------------------------------------------------
// FP16 GEMM-NT device core (cp.async 3-stage, K-slab 32, m16n8k16).
#define CAS  3
#define ROWH 40

template<int AMODE, int NT, int HOUT, int MT>
__device__ __forceinline__
void gemm_dev(const __half* __restrict__ A, const __half* __restrict__ Bw,
              const float* __restrict__ bias, void* __restrict__ Cv,
              int N, int K, int lda, int ldb,
              long long sAz, long long sBz, long long sCz,
              const int* __restrict__ cxs, const int* __restrict__ cys,
              int bx, int by, int bz)
{
    constexpr int STG_A = MT * ROWH;
    constexpr int STG_B = NT * ROWH;
    constexpr int WNW   = (NT == 128) ? 4 : 2;
    constexpr int MF    = MT * WNW / 128;

    extern __shared__ __half smh[];
    const uint32_t smBase = (uint32_t)__cvta_generic_to_shared(smh);

    const int bm = by * MT;
    const int bn = bx * NT;
    int cellBase = 0;
    if (AMODE == 1) cellBase = cxs[bz] * 512 + cys[bz] * 8;
    if (AMODE == 0) A += (long long)bz * sAz;
    Bw += (long long)bz * sBz;

    const int tid  = threadIdx.x;
    const int lane = tid & 31;
    const int wid  = tid >> 5;
    const int wm   = wid / WNW;
    const int wn   = wid % WNW;
    const int g    = lane >> 2;
    const int t2   = (lane & 3) * 2;
    const int alr  = (MT == 128) ? (tid >> 1) : (tid >> 2);
    const int alk  = (MT == 128) ? (tid & 1) * 16 : (tid & 3) * 8;
    const int br   = (NT == 128) ? (tid >> 1) : (tid >> 2);
    const int bc   = (NT == 128) ? (tid & 1) * 16 : (tid & 3) * 8;

    float acc[MF][4][4];
#pragma unroll
    for (int i = 0; i < MF; i++)
#pragma unroll
        for (int j = 0; j < 4; j++)
#pragma unroll
            for (int q = 0; q < 4; q++) acc[i][j][q] = 0.f;

    auto issue = [&](int stg, int k0) {
        const __half *ap0, *ap1;
        if (AMODE == 0) {
            ap0 = A + (long long)(bm + alr) * lda + k0 + alk;
            ap1 = ap0 + 8;
        } else {
            const int tt = k0 + alk;
            const __half* base = A + (long long)(bm + alr) * 4096 + cellBase;
            ap0 = base + ((tt >> 3) << 6);
            ap1 = base + (((tt + 8) >> 3) << 6);
        }
        const uint32_t da = smBase + 2u * (stg * STG_A + alr * ROWH + alk);
        cp16(da, ap0);
        if (MT == 128) cp16(da + 16, ap1);
        const __half* bp = Bw + (long long)(bn + br) * ldb + k0 + bc;
        const uint32_t db = smBase + 2u * (CAS * STG_A + stg * STG_B + br * ROWH + bc);
        cp16(db, bp);
        if (NT == 128) cp16(db + 16, bp + 8);
    };

    const int nIter = K >> 5;
#pragma unroll
    for (int s = 0; s < CAS - 1; s++) {
        if (s < nIter) issue(s, s * 32);
        asm volatile("cp.async.commit_group;");
    }

    for (int it = 0; it < nIter; it++) {
        const int cur = it % CAS;
        asm volatile("cp.async.wait_group %0;" :: "n"(CAS - 2));
        __syncthreads();

        const __half* Ab = smh + cur * STG_A;
        const __half* Bb = smh + CAS * STG_A + cur * STG_B;
#pragma unroll
        for (int kk = 0; kk < 32; kk += 16) {
            uint32_t af[MF][4], bf[4][2];
#pragma unroll
            for (int i = 0; i < MF; i++) {
                const int m = wm * (MF * 16) + i * 16;
                af[i][0] = *reinterpret_cast<const uint32_t*>(Ab + (m + g) * ROWH + kk + t2);
                af[i][1] = *reinterpret_cast<const uint32_t*>(Ab + (m + 8 + g) * ROWH + kk + t2);
                af[i][2] = *reinterpret_cast<const uint32_t*>(Ab + (m + g) * ROWH + kk + t2 + 8);
                af[i][3] = *reinterpret_cast<const uint32_t*>(Ab + (m + 8 + g) * ROWH + kk + t2 + 8);
            }
#pragma unroll
            for (int j = 0; j < 4; j++) {
                const int n = wn * 32 + j * 8;
                bf[j][0] = *reinterpret_cast<const uint32_t*>(Bb + (n + g) * ROWH + kk + t2);
                bf[j][1] = *reinterpret_cast<const uint32_t*>(Bb + (n + g) * ROWH + kk + t2 + 8);
            }
#pragma unroll
            for (int i = 0; i < MF; i++)
#pragma unroll
                for (int j = 0; j < 4; j++) mma_f16(acc[i][j], af[i], bf[j]);
        }
        const int nk = it + CAS - 1;
        if (nk < nIter) issue(nk % CAS, nk * 32);
        asm volatile("cp.async.commit_group;");
    }

    float* Cf = (float*)Cv;
    __half* Ch = (__half*)Cv;
#pragma unroll
    for (int i = 0; i < MF; i++) {
        const int row0 = bm + wm * (MF * 16) + i * 16 + g;
#pragma unroll
        for (int j = 0; j < 4; j++) {
            const int col = bn + wn * 32 + j * 8 + t2;
            float bz0 = 0.f, bz1 = 0.f;
            if (bias) { bz0 = __ldg(&bias[col]); bz1 = __ldg(&bias[col + 1]); }
            const float v0 = acc[i][j][0] + bz0, v1 = acc[i][j][1] + bz1;
            const float v2 = acc[i][j][2] + bz0, v3 = acc[i][j][3] + bz1;
            if (HOUT == 0) {
                float* C = Cf + (long long)bz * sCz;
                *reinterpret_cast<float2*>(&C[(long long)row0 * N + col]) = make_float2(v0, v1);
                *reinterpret_cast<float2*>(&C[(long long)(row0 + 8) * N + col]) = make_float2(v2, v3);
            } else {
                __half* C = Ch + (long long)bz * sCz;
                *reinterpret_cast<__half2*>(&C[(long long)row0 * N + col]) =
                    __floats2half2_rn(v0, v1);
                *reinterpret_cast<__half2*>(&C[(long long)(row0 + 8) * N + col]) =
                    __floats2half2_rn(v2, v3);
            }
        }
    }
}

// ---------------------------------------------------------------------------
// gi2 multi-cell: one 128x128 tile position, ZCH cells per block.
#define ROW2 72

__device__ __forceinline__
void gi2_multi(const __half* __restrict__ xh, const __half* __restrict__ w2ph,
               const float* __restrict__ b2p, __half* __restrict__ gi2h,
               const int* __restrict__ cxs, const int* __restrict__ cys,
               int bx, int by, int z0, int zn, int B)
{
    extern __shared__ __half smh[];
    const uint32_t smBase = (uint32_t)__cvta_generic_to_shared(smh);
    const uint32_t bOff = 2 * 128 * ROW2;

    const int bm = by * 128;
    const int bn = bx * 128;

    const int tid  = threadIdx.x;
    const int lane = tid & 31;
    const int wid  = tid >> 5;
    const int wm   = wid >> 2;
    const int wn   = wid & 3;
    const int g    = lane >> 2;
    const int t2   = (lane & 3) * 2;
    const int lr   = tid >> 1;
    const int lc   = (tid & 1) * 32;

    auto issueA = [&](int buf, int zi) {
        const int cellBase = cxs[z0 + zi] * 512 + cys[z0 + zi] * 8;
        const __half* base = xh + (long long)(bm + lr) * 4096 + cellBase + (lc >> 3) * 64;
        const uint32_t da = smBase + 2u * ((buf * 128 + lr) * ROW2 + lc);
#pragma unroll
        for (int q = 0; q < 4; q++)
            cp16(da + q * 16, base + q * 64);
    };

    {
        const __half* bp = w2ph + (long long)(bn + lr) * 64 + lc;
        const uint32_t db = smBase + 2u * (bOff + lr * ROW2 + lc);
#pragma unroll
        for (int q = 0; q < 4; q++)
            cp16(db + q * 16, bp + q * 8);
    }
    issueA(0, 0);
    asm volatile("cp.async.commit_group;");

    float bzv[4][2];
#pragma unroll
    for (int j = 0; j < 4; j++) {
        const int col = bn + wn * 32 + j * 8 + t2;
        bzv[j][0] = __ldg(&b2p[col]);
        bzv[j][1] = __ldg(&b2p[col + 1]);
    }

    const __half* Bs = smh + bOff;
    for (int zi = 0; zi < zn; zi++) {
        if (zi + 1 < zn) issueA((zi + 1) & 1, zi + 1);
        asm volatile("cp.async.commit_group;");
        asm volatile("cp.async.wait_group 1;");
        __syncthreads();

        const __half* Ab = smh + ((zi & 1) * 128) * ROW2;
        float acc[4][4][4];
#pragma unroll
        for (int i = 0; i < 4; i++)
#pragma unroll
            for (int j = 0; j < 4; j++)
#pragma unroll
                for (int q = 0; q < 4; q++) acc[i][j][q] = 0.f;

#pragma unroll
        for (int kk = 0; kk < 64; kk += 16) {
            uint32_t af[4][4], bf[4][2];
#pragma unroll
            for (int i = 0; i < 4; i++) {
                const int m = wm * 64 + i * 16;
                af[i][0] = *reinterpret_cast<const uint32_t*>(Ab + (m + g) * ROW2 + kk + t2);
                af[i][1] = *reinterpret_cast<const uint32_t*>(Ab + (m + 8 + g) * ROW2 + kk + t2);
                af[i][2] = *reinterpret_cast<const uint32_t*>(Ab + (m + g) * ROW2 + kk + t2 + 8);
                af[i][3] = *reinterpret_cast<const uint32_t*>(Ab + (m + 8 + g) * ROW2 + kk + t2 + 8);
            }
#pragma unroll
            for (int j = 0; j < 4; j++) {
                const int n = wn * 32 + j * 8;
                bf[j][0] = *reinterpret_cast<const uint32_t*>(Bs + (n + g) * ROW2 + kk + t2);
                bf[j][1] = *reinterpret_cast<const uint32_t*>(Bs + (n + g) * ROW2 + kk + t2 + 8);
            }
#pragma unroll
            for (int i = 0; i < 4; i++)
#pragma unroll
                for (int j = 0; j < 4; j++) mma_f16(acc[i][j], af[i], bf[j]);
        }

        __half* C = gi2h + (long long)(z0 + zi) * B * 768;
#pragma unroll
        for (int i = 0; i < 4; i++) {
            const int row0 = bm + wm * 64 + i * 16 + g;
#pragma unroll
            for (int j = 0; j < 4; j++) {
                const int col = bn + wn * 32 + j * 8 + t2;
                *reinterpret_cast<__half2*>(&C[(long long)row0 * 768 + col]) =
                    __floats2half2_rn(acc[i][j][0] + bzv[j][0], acc[i][j][1] + bzv[j][1]);
                *reinterpret_cast<__half2*>(&C[(long long)(row0 + 8) * 768 + col]) =
                    __floats2half2_rn(acc[i][j][2] + bzv[j][0], acc[i][j][3] + bzv[j][1]);
            }
        }
        __syncthreads();
    }
}

// ---------------------------------------------------------------------------
// big_fused: x1-splitK | gh12(->fp16) | gi2-multi(all cells)
__global__ __launch_bounds__(256)
void big_fused(const __half* __restrict__ xh, const __half* __restrict__ e1h,
               const __half* __restrict__ hh, const __half* __restrict__ whhh,
               const float* __restrict__ bhh, const __half* __restrict__ w2ph,
               const float* __restrict__ b2p,
               float* __restrict__ xp, __half* __restrict__ gh12h,
               __half* __restrict__ gi2h,
               const int* __restrict__ cxs, const int* __restrict__ cys,
               int MB, int nX1, int nGH, int Kc, int B)
{
    const int i = blockIdx.x;
    if (i < nX1) {
        const int bx = i & 1, r = i >> 1;
        gemm_dev<0, 128, 0, 128>(xh, e1h, nullptr, xp, 256, 1024, 4096, 4096,
                                 1024, 1024, (long long)B * 256, nullptr, nullptr,
                                 bx, r % MB, r / MB);
    } else if (i < nX1 + nGH) {
        const int j = i - nX1;
        gemm_dev<0, 128, 1, 128>(hh, whhh, bhh, gh12h, 1536, 256, 256, 256,
                                 0, 0, 0, nullptr, nullptr,
                                 j % 12, j / 12, 0);
    } else {
        const int k = i - nX1 - nGH;
        const int bx = k % 6, r = k / 6;
        const int by = r % MB, zg = r / MB;
        const int z0 = zg * ZCH;
        const int zn = (Kc - z0 < ZCH) ? (Kc - z0) : ZCH;
        gi2_multi(xh, w2ph, b2p, gi2h, cxs, cys, bx, by, z0, zn, B);
    }
}

// ---------------------------------------------------------------------------
// GRU 8-elems/thread core (fp16 gi + fp16 gh)
__device__ __forceinline__
void gru8_core(const __half* __restrict__ g, const __half* __restrict__ q,
               const float* __restrict__ h0, float* __restrict__ hout,
               __half* __restrict__ h16, long long zslot, int idx, long long Bll)
{
    const int b = idx >> 5;
    const int j = (idx & 31) * 8;
    const __half* gp = g + (long long)b * 768;
    const __half* qp = q + (long long)b * 1536;

    const uint4 irU = *reinterpret_cast<const uint4*>(gp + j);
    const uint4 izU = *reinterpret_cast<const uint4*>(gp + 256 + j);
    const uint4 inU = *reinterpret_cast<const uint4*>(gp + 512 + j);
    const uint4 hrU = *reinterpret_cast<const uint4*>(qp + j);
    const uint4 hzU = *reinterpret_cast<const uint4*>(qp + 256 + j);
    const uint4 hnU = *reinterpret_cast<const uint4*>(qp + 512 + j);
    const __half2* irh = reinterpret_cast<const __half2*>(&irU);
    const __half2* izh = reinterpret_cast<const __half2*>(&izU);
    const __half2* inh = reinterpret_cast<const __half2*>(&inU);
    const __half2* hrh = reinterpret_cast<const __half2*>(&hrU);
    const __half2* hzh = reinterpret_cast<const __half2*>(&hzU);
    const __half2* hnh = reinterpret_cast<const __half2*>(&hnU);

    const long long obase = zslot * (Bll * 256) + (long long)b * 256 + j;

#pragma unroll
    for (int hfi = 0; hfi < 2; hfi++) {
        const int jj = j + hfi * 4;
        const float4 hh = *reinterpret_cast<const float4*>(h0 + (long long)b * 256 + jj);
        const float2 ir01 = __half22float2(irh[hfi * 2]);
        const float2 ir23 = __half22float2(irh[hfi * 2 + 1]);
        const float2 iz01 = __half22float2(izh[hfi * 2]);
        const float2 iz23 = __half22float2(izh[hfi * 2 + 1]);
        const float2 in01 = __half22float2(inh[hfi * 2]);
        const float2 in23 = __half22float2(inh[hfi * 2 + 1]);
        const float2 hr01 = __half22float2(hrh[hfi * 2]);
        const float2 hr23 = __half22float2(hrh[hfi * 2 + 1]);
        const float2 hz01 = __half22float2(hzh[hfi * 2]);
        const float2 hz23 = __half22float2(hzh[hfi * 2 + 1]);
        const float2 hn01 = __half22float2(hnh[hfi * 2]);
        const float2 hn23 = __half22float2(hnh[hfi * 2 + 1]);

        float4 r;
        { const float rr = sigf(ir01.x + hr01.x), zz = sigf(iz01.x + hz01.x);
          r.x = (1.f - zz) * tanhfast(in01.x + rr * hn01.x) + zz * hh.x; }
        { const float rr = sigf(ir01.y + hr01.y), zz = sigf(iz01.y + hz01.y);
          r.y = (1.f - zz) * tanhfast(in01.y + rr * hn01.y) + zz * hh.y; }
        { const float rr = sigf(ir23.x + hr23.x), zz = sigf(iz23.x + hz23.x);
          r.z = (1.f - zz) * tanhfast(in23.x + rr * hn23.x) + zz * hh.z; }
        { const float rr = sigf(ir23.y + hr23.y), zz = sigf(iz23.y + hz23.y);
          r.w = (1.f - zz) * tanhfast(in23.y + rr * hn23.y) + zz * hh.w; }

        *reinterpret_cast<float4*>(hout + obase + hfi * 4) = r;
        reinterpret_cast<__half2*>(h16 + obase + hfi * 4)[0] = __floats2half2_rn(r.x, r.y);
        reinterpret_cast<__half2*>(h16 + obase + hfi * 4)[1] = __floats2half2_rn(r.z, r.w);
    }
}

// ---------------------------------------------------------------------------
// gi1 (64x64 tiles, 30KB smem) ∥ gru-cells — low-smem homogeneous merge.
__global__ __launch_bounds__(256)
void gi1_gru_cells(const __half* __restrict__ x1h, const __half* __restrict__ wi1h,
                   const float* __restrict__ bih1, __half* __restrict__ gi1h,
                   const __half* __restrict__ gi2h, const __half* __restrict__ gh12h,
                   const float* __restrict__ h0,
                   float* __restrict__ hout, __half* __restrict__ h16,
                   int nGi1, int B)
{
    const int i = blockIdx.x;
    if (i < nGi1) {
        gemm_dev<0, 64, 1, 64>(x1h, wi1h, bih1, gi1h, 768, 256, 256, 256,
                               0, 0, 0, nullptr, nullptr,
                               i % 12, i / 12, 0);
    } else {
        const int j = i - nGi1;
        const int z = j >> 8;                       // 256 blocks per cell
        const int idx = (j & 255) * 256 + threadIdx.x;   // over B*32
        if (idx < B * 32)
            gru8_core(gi2h + (long long)z * B * 768, gh12h + 768, h0,
                      hout, h16, z + 1, idx, (long long)B);
    }
}

// gru layer-1
__global__ void gru_l1_kernel(const __half* __restrict__ gi1h, const __half* __restrict__ gh12h,
                              const float* __restrict__ h0,
                              float* __restrict__ hout, __half* __restrict__ h16, int B)
{
    const int idx = blockIdx.x * blockDim.x + threadIdx.x;
    if (idx < B * 32)
        gru8_core(gi1h, gh12h, h0, hout, h16, 0, idx, (long long)B);
}

// merged o GEMM
__global__ __launch_bounds__(256)
void o_gemm(const __half* __restrict__ A,
            const __half* __restrict__ Bw, const __half* __restrict__ Bw2,
            const float* __restrict__ bias, const float* __restrict__ bias2,
            float* __restrict__ C, int B)
{
    const __half* B_ = (blockIdx.z > 0) ? Bw2 : Bw;
    const float* bi  = (blockIdx.z > 0) ? bias2 : bias;
    gemm_dev<0, 64, 0, 128>(A, B_, bi, C, 64, 256, 256, 256,
                            (long long)B * 256, 0, (long long)B * 64,
                            nullptr, nullptr, blockIdx.x, blockIdx.y, blockIdx.z);
}

// ---------------------------------------------------------------------------
__global__ void reduce_x1_kernel(const float* __restrict__ P, const float* __restrict__ bias,
                                 __half* __restrict__ x1, int n4)
{
    const int idx = blockIdx.x * blockDim.x + threadIdx.x;
    if (idx >= n4) return;
    const float4 p0 = *reinterpret_cast<const float4*>(P + (size_t)0 * BSZ * 256 + idx * 4);
    const float4 p1 = *reinterpret_cast<const float4*>(P + (size_t)1 * BSZ * 256 + idx * 4);
    const float4 p2 = *reinterpret_cast<const float4*>(P + (size_t)2 * BSZ * 256 + idx * 4);
    const float4 p3 = *reinterpret_cast<const float4*>(P + (size_t)3 * BSZ * 256 + idx * 4);
    const int j0 = (idx * 4) & 255;
    const float4 b = *reinterpret_cast<const float4*>(bias + j0);
    reinterpret_cast<__half2*>(x1)[idx * 2] =
        __floats2half2_rn(p0.x + p1.x + p2.x + p3.x + b.x,
                          p0.y + p1.y + p2.y + p3.y + b.y);
    reinterpret_cast<__half2*>(x1)[idx * 2 + 1] =
        __floats2half2_rn(p0.z + p1.z + p2.z + p3.z + b.z,
                          p0.w + p1.w + p2.w + p3.w + b.w);
}

// ---------------------------------------------------------------------------
__global__ void assemble_y_kernel(const float* __restrict__ o1, const float* __restrict__ o2,
                                  const int* __restrict__ cmap, float* __restrict__ y, int n4)
{
    const int idx = blockIdx.x * blockDim.x + threadIdx.x;
    if (idx >= n4) return;
    const int b   = idx >> 10;
    const int rem = idx & 1023;
    const int i   = rem >> 4;
    const int j0  = (rem & 15) * 4;
    const float v = __ldg(&o1[b * 64 + i]);
    float4 r = make_float4(v, v, v, v);
    const int k = cmap[(i >> 3) * 8 + (j0 >> 3)];
    if (k >= 0) {
        const int t = (i & 7) * 8 + (j0 & 7);
        const float4 a = *reinterpret_cast<const float4*>(o2 + ((long long)k * BSZ + b) * 64 + t);
        r.x += a.x; r.y += a.y; r.z += a.z; r.w += a.w;
    }
    *reinterpret_cast<float4*>(y + (long long)idx * 4) = r;
}

// ---------------------------------------------------------------------------
extern "C" void kernel_launch(void* const* d_in, const int* in_sizes, int n_in,
                              void* d_out, int out_size)
{
    const float* x    = (const float*)d_in[0];
    const float* h    = (const float*)d_in[1];
    const float* fa   = (const float*)d_in[2];
    const float* e1w  = (const float*)d_in[3];
    const float* e1b  = (const float*)d_in[4];
    const float* wih1 = (const float*)d_in[5];
    const float* whh1 = (const float*)d_in[6];
    const float* bih1 = (const float*)d_in[7];
    const float* bhh1 = (const float*)d_in[8];
    const float* o1w  = (const float*)d_in[9];
    const float* o1b  = (const float*)d_in[10];
    const float* e2w  = (const float*)d_in[11];
    const float* e2b  = (const float*)d_in[12];
    const float* wih2 = (const float*)d_in[13];
    const float* whh2 = (const float*)d_in[14];
    const float* bih2 = (const float*)d_in[15];
    const float* bhh2 = (const float*)d_in[16];
    const float* o2w  = (const float*)d_in[17];
    const float* o2b  = (const float*)d_in[18];
    float* out = (float*)d_out;

    const int B = in_sizes[0] / 4096;                  // 2048
    const long long YOFF = (long long)B * 4096;
    int Kc = (int)(((long long)out_size - YOFF) / ((long long)B * 256)) - 1;
    if (Kc < 0) Kc = 0;
    if (Kc > MAXK) Kc = MAXK;

    __half *p_xh, *p_hh, *p_e1h, *p_wi1h, *p_whhh, *p_o1wh, *p_o2wh,
           *p_x1h, *p_gi1h, *p_gi2h, *p_hh16, *p_w2ph, *p_gh12h;
    float *p_bhh, *p_xp, *p_o, *p_b2p;
    int *p_cx, *p_cy, *p_cmap;
    cudaGetSymbolAddress((void**)&p_xh,    d_xh);
    cudaGetSymbolAddress((void**)&p_hh,    d_hh);
    cudaGetSymbolAddress((void**)&p_e1h,   d_e1h);
    cudaGetSymbolAddress((void**)&p_wi1h,  d_wi1h);
    cudaGetSymbolAddress((void**)&p_whhh,  d_whhh);
    cudaGetSymbolAddress((void**)&p_bhh,   d_bhh);
    cudaGetSymbolAddress((void**)&p_o1wh,  d_o1wh);
    cudaGetSymbolAddress((void**)&p_o2wh,  d_o2wh);
    cudaGetSymbolAddress((void**)&p_xp,    d_xp);
    cudaGetSymbolAddress((void**)&p_x1h,   d_x1h);
    cudaGetSymbolAddress((void**)&p_gh12h, d_gh12h);
    cudaGetSymbolAddress((void**)&p_gi1h,  d_gi1h);
    cudaGetSymbolAddress((void**)&p_gi2h,  d_gi2h);
    cudaGetSymbolAddress((void**)&p_hh16,  d_hh16);
    cudaGetSymbolAddress((void**)&p_o,     d_o);
    cudaGetSymbolAddress((void**)&p_w2ph,  d_w2ph);
    cudaGetSymbolAddress((void**)&p_b2p,   d_b2p);
    cudaGetSymbolAddress((void**)&p_cx,    d_cx);
    cudaGetSymbolAddress((void**)&p_cy,    d_cy);
    cudaGetSymbolAddress((void**)&p_cmap,  d_cmap);

    const int SMB128 = 2 * CAS * (128 * ROWH + 128 * ROWH);  // 61440
    const int SMB64  = 2 * CAS * (128 * ROWH + 64 * ROWH);   // 46080
    const int SMB44  = 2 * CAS * (64 * ROWH + 64 * ROWH);    // 30720
    cudaFuncSetAttribute((const void*)big_fused,     cudaFuncAttributeMaxDynamicSharedMemorySize, SMB128);
    cudaFuncSetAttribute((const void*)gi1_gru_cells, cudaFuncAttributeMaxDynamicSharedMemorySize, SMB44);
    cudaFuncSetAttribute((const void*)o_gemm,        cudaFuncAttributeMaxDynamicSharedMemorySize, SMB64);

    float* yh0 = out + YOFF;
    const int MB = B / 128;                       // 16
    const int nPrep = B * 4 + B / 4 + 1024 + 192 + 16 + 16 + 384 + 192 + 1;

    // 1) prep
    prep_kernel<<<nPrep, 256>>>(x, h, e1w, wih1, o1w, o2w, whh1, whh2, bhh1, bhh2,
                                wih2, e2w, e2b, bih2, fa,
                                p_xh, p_hh, p_e1h, p_wi1h, p_o1wh, p_o2wh,
                                p_whhh, p_bhh, p_w2ph, p_b2p,
                                p_cx, p_cy, p_cmap, B);

    // 2) x1-splitK ∥ gh12(->fp16) ∥ gi2-multi
    const int nX1  = 2 * MB * 4;
    const int nGH  = 12 * MB;
    const int nZG  = (Kc + ZCH - 1) / ZCH;
    const int nGI2 = 6 * MB * nZG;
    big_fused<<<nX1 + nGH + nGI2, 256, SMB128>>>(
        p_xh, p_e1h, p_hh, p_whhh, p_bhh, p_w2ph, p_b2p,
        p_xp, p_gh12h, p_gi2h, p_cx, p_cy, MB, nX1, nGH, Kc, B);

    // 3) reduce -> fp16 x1
    reduce_x1_kernel<<<(B * 64 + 255) / 256, 256>>>(p_xp, e1b, p_x1h, B * 64);

    // 4) gi1 (64x64, 30KB smem) ∥ gru-cells (fp16 gh)
    const int nGi1 = 12 * (B / 64);                 // 384
    const int nGruC = ((B * 32 + 255) / 256) * Kc;  // 256 * Kc
    gi1_gru_cells<<<nGi1 + nGruC, 256, SMB44>>>(
        p_x1h, p_wi1h, bih1, p_gi1h, p_gi2h, p_gh12h, h, yh0, p_hh16, nGi1, B);

    // 5) gru layer-1
    gru_l1_kernel<<<(B * 32 + 255) / 256, 256>>>(p_gi1h, p_gh12h, h, yh0, p_hh16, B);

    // 6) merged o GEMM
    o_gemm<<<dim3(1, MB, Kc + 1), 256, SMB64>>>(p_hh16, p_o1wh, p_o2wh, o1b, o2b, p_o, B);

    // 7) y = bcast(o1) + scatter(o2)
    assemble_y_kernel<<<(B * 1024 + 255) / 256, 256>>>(p_o, p_o + (long long)B * 64,
                                                       p_cmap, out, B * 1024);
}